// round 10
// baseline (speedup 1.0000x reference)
#include <cuda_runtime.h>
#include <cuda_bf16.h>
#include <math.h>
#include <stdint.h>

// ---------------- problem constants ----------------
#define BB      4
#define SS      2048
#define HIDDEN  1024
#define HEADS   16
#define DH      64
#define LAYERS  4
#define IN_DIM  512
#define OUT_DIM 1024
#define FF_DIM  4096
#define M_ROWS  (BB * SS)          // 8192

// ---------------- scratch (no allocation allowed) ----------------
__device__ float g_h  [(size_t)M_ROWS * HIDDEN];
__device__ float g_qkv[(size_t)M_ROWS * 3 * HIDDEN];
__device__ float g_ctx[(size_t)M_ROWS * HIDDEN];
__device__ float g_y  [(size_t)M_ROWS * HIDDEN];
__device__ float g_ff [(size_t)M_ROWS * FF_DIM];

// ---------------- tf32 helpers ----------------
__device__ __forceinline__ float tf32r(float x) {
    uint32_t u;
    asm("cvt.rna.tf32.f32 %0, %1;" : "=r"(u) : "f"(x));
    return __uint_as_float(u);
}
__device__ __forceinline__ void split4(float4 v, float4& hi, float4& lo) {
    hi.x = tf32r(v.x); lo.x = tf32r(v.x - hi.x);
    hi.y = tf32r(v.y); lo.y = tf32r(v.y - hi.y);
    hi.z = tf32r(v.z); lo.z = tf32r(v.z - hi.z);
    hi.w = tf32r(v.w); lo.w = tf32r(v.w - hi.w);
}
// D = A(16x8,row) * B(8x8,col) + D, tf32 inputs, f32 accum
__device__ __forceinline__ void mma_tf32(float* c, const float* a, const float* b) {
    asm volatile(
        "mma.sync.aligned.m16n8k8.row.col.f32.tf32.tf32.f32 "
        "{%0,%1,%2,%3}, {%4,%5,%6,%7}, {%8,%9}, {%0,%1,%2,%3};\n"
        : "+f"(c[0]), "+f"(c[1]), "+f"(c[2]), "+f"(c[3])
        : "r"(__float_as_uint(a[0])), "r"(__float_as_uint(a[1])),
          "r"(__float_as_uint(a[2])), "r"(__float_as_uint(a[3])),
          "r"(__float_as_uint(b[0])), "r"(__float_as_uint(b[1])));
}
// 3xTF32: c += Ahi*Bhi + Ahi*Blo + Alo*Bhi
__device__ __forceinline__ void mma3(float* c, const float* ah, const float* al,
                                     const float* bh, const float* bl) {
    mma_tf32(c, ah, bl);
    mma_tf32(c, al, bh);
    mma_tf32(c, ah, bh);
}

// =================================================================
// Tensor-core GEMM (3xTF32): C[M,N] = A[M,K] @ W[K,N] + bias
// EPI: 0 = bias, 1 = bias+relu, 2 = bias then *32 + posenc
// BM=BN=128, BK=16, 256 threads (8 warps, 2x4), warp tile 64x32.
// Double-buffered dynamic smem, 2 CTAs/SM.  (R6 proven version)
// =================================================================
#define A_SZ  (128 * 20)     // floats per A tile (stride 20: conflict-free frag loads)
#define B_SZ  (16 * 132)     // floats per B tile (stride 132: near-conflict-free)
#define STG   (2 * A_SZ + 2 * B_SZ)                 // floats per stage
#define GEMM_SMEM (2 * STG * sizeof(float))         // 74752 B

template<int EPI>
__global__ void __launch_bounds__(256, 2)
gemm_tc(const float* __restrict__ A, const float* __restrict__ W,
        const float* __restrict__ bias, float* __restrict__ C,
        int M, int N, int K)
{
    extern __shared__ __align__(16) float smp[];

    const int tid = threadIdx.x;
    const int cb = blockIdx.x * 128;
    const int rb = blockIdx.y * 128;

    const int arow = tid >> 2;          // 0..63
    const int acol = (tid & 3) * 4;     // 0,4,8,12
    const int brow = tid >> 5;          // 0..7
    const int bcol = (tid & 31) * 4;    // 0..124

    const float* Ap0 = A + (size_t)(rb + arow) * K + acol;
    const float* Ap1 = Ap0 + (size_t)64 * K;
    const float* Wp0 = W + (size_t)brow * N + cb + bcol;
    const float* Wp1 = Wp0 + (size_t)8 * N;

    const int wid = tid >> 5, lane = tid & 31;
    const int grp = lane >> 2, t4 = lane & 3;
    const int m0 = (wid >> 2) * 64;     // 0 or 64
    const int n0 = (wid & 3) * 32;      // 0,32,64,96

    float acc[4][4][4];
#pragma unroll
    for (int mt = 0; mt < 4; mt++)
#pragma unroll
        for (int nt = 0; nt < 4; nt++)
#pragma unroll
            for (int j = 0; j < 4; j++) acc[mt][nt][j] = 0.f;

    // ---- prologue: load + split + store tile 0 ----
    {
        float4 ra0 = *(const float4*)(Ap0);
        float4 ra1 = *(const float4*)(Ap1);
        float4 rb0 = *(const float4*)(Wp0);
        float4 rb1 = *(const float4*)(Wp1);
        float* Ah = smp;  float* Al = Ah + A_SZ;
        float* Bh = Al + A_SZ;  float* Bl = Bh + B_SZ;
        float4 h, l;
        split4(ra0, h, l); *(float4*)&Ah[arow * 20 + acol]        = h; *(float4*)&Al[arow * 20 + acol]        = l;
        split4(ra1, h, l); *(float4*)&Ah[(arow + 64) * 20 + acol] = h; *(float4*)&Al[(arow + 64) * 20 + acol] = l;
        split4(rb0, h, l); *(float4*)&Bh[brow * 132 + bcol]       = h; *(float4*)&Bl[brow * 132 + bcol]       = l;
        split4(rb1, h, l); *(float4*)&Bh[(brow + 8) * 132 + bcol] = h; *(float4*)&Bl[(brow + 8) * 132 + bcol] = l;
    }
    __syncthreads();

    int cur = 0;
    for (int k0 = 0; k0 < K; k0 += 16) {
        const bool more = (k0 + 16 < K);
        float4 ra0, ra1, rb0, rb1;
        if (more) {    // global prefetch overlaps the mma below
            ra0 = *(const float4*)(Ap0 + k0 + 16);
            ra1 = *(const float4*)(Ap1 + k0 + 16);
            rb0 = *(const float4*)(Wp0 + (size_t)(k0 + 16) * N);
            rb1 = *(const float4*)(Wp1 + (size_t)(k0 + 16) * N);
        }

        const float* Ah = smp + cur * STG;
        const float* Al = Ah + A_SZ;
        const float* Bh = Al + A_SZ;
        const float* Bl = Bh + B_SZ;

#pragma unroll
        for (int k8 = 0; k8 < 16; k8 += 8) {
            float ah[4][4], al[4][4], bh[4][2], bl[4][2];
#pragma unroll
            for (int mt = 0; mt < 4; mt++) {
                int mr = m0 + mt * 16 + grp;
                ah[mt][0] = Ah[mr * 20 + k8 + t4];
                ah[mt][1] = Ah[(mr + 8) * 20 + k8 + t4];
                ah[mt][2] = Ah[mr * 20 + k8 + t4 + 4];
                ah[mt][3] = Ah[(mr + 8) * 20 + k8 + t4 + 4];
                al[mt][0] = Al[mr * 20 + k8 + t4];
                al[mt][1] = Al[(mr + 8) * 20 + k8 + t4];
                al[mt][2] = Al[mr * 20 + k8 + t4 + 4];
                al[mt][3] = Al[(mr + 8) * 20 + k8 + t4 + 4];
            }
#pragma unroll
            for (int nt = 0; nt < 4; nt++) {
                int nc = n0 + nt * 8 + grp;
                bh[nt][0] = Bh[(k8 + t4) * 132 + nc];
                bh[nt][1] = Bh[(k8 + t4 + 4) * 132 + nc];
                bl[nt][0] = Bl[(k8 + t4) * 132 + nc];
                bl[nt][1] = Bl[(k8 + t4 + 4) * 132 + nc];
            }
#pragma unroll
            for (int mt = 0; mt < 4; mt++)
#pragma unroll
                for (int nt = 0; nt < 4; nt++)
                    mma3(acc[mt][nt], ah[mt], al[mt], bh[nt], bl[nt]);
        }

        if (more) {
            // write the OTHER stage (nobody reads it yet) then one sync
            float* Awh = smp + (cur ^ 1) * STG;
            float* Awl = Awh + A_SZ;
            float* Bwh = Awl + A_SZ;
            float* Bwl = Bwh + B_SZ;
            float4 h, l;
            split4(ra0, h, l); *(float4*)&Awh[arow * 20 + acol]        = h; *(float4*)&Awl[arow * 20 + acol]        = l;
            split4(ra1, h, l); *(float4*)&Awh[(arow + 64) * 20 + acol] = h; *(float4*)&Awl[(arow + 64) * 20 + acol] = l;
            split4(rb0, h, l); *(float4*)&Bwh[brow * 132 + bcol]       = h; *(float4*)&Bwl[brow * 132 + bcol]       = l;
            split4(rb1, h, l); *(float4*)&Bwh[(brow + 8) * 132 + bcol] = h; *(float4*)&Bwl[(brow + 8) * 132 + bcol] = l;
            __syncthreads();
            cur ^= 1;
        }
    }

    // ---- epilogue ----
#pragma unroll
    for (int mt = 0; mt < 4; mt++) {
#pragma unroll
        for (int nt = 0; nt < 4; nt++) {
            int col = cb + n0 + nt * 8 + 2 * t4;
            float b0 = bias[col], b1 = bias[col + 1];
#pragma unroll
            for (int half = 0; half < 2; half++) {
                int row = rb + m0 + mt * 16 + grp + half * 8;
                float c0 = acc[mt][nt][half * 2 + 0] + b0;
                float c1 = acc[mt][nt][half * 2 + 1] + b1;
                if (EPI == 1) { c0 = fmaxf(c0, 0.f); c1 = fmaxf(c1, 0.f); }
                if (EPI == 2) {
                    int srow = row & (SS - 1);
                    float f0 = expf(-9.210340371976184f * (float)(col & ~1) * (1.0f / 1024.0f));
                    float f1 = expf(-9.210340371976184f * (float)((col + 1) & ~1) * (1.0f / 1024.0f));
                    float a0 = (float)srow * f0, a1 = (float)srow * f1;
                    float p0 = (col & 1) ? cosf(a0) : sinf(a0);
                    float p1 = ((col + 1) & 1) ? cosf(a1) : sinf(a1);
                    c0 = c0 * 32.0f + p0;
                    c1 = c1 * 32.0f + p1;
                }
                float2 o = {c0, c1};
                *(float2*)(C + (size_t)row * N + col) = o;
            }
        }
    }
}

// =================================================================
// Flash attention, 3xTF32 tensor cores, register-prefetched K/V.
// Block = (b, h, 128 q-rows), 256 threads = 8 warps, warp owns 16 q rows.
// Per kt: split+STS (fast) -> sync -> prefetch next K/V into regs
// (overlaps compute) -> compute -> sync.
// =================================================================
#define ASTR 68
#define ATTN_SMEM ((2 * 128 * ASTR + 2 * 64 * ASTR + 2 * 64 * ASTR + 2 * 128 * ASTR) * sizeof(float))  // 208896

__global__ void __launch_bounds__(256)
attn_tc(const float* __restrict__ qkv, float* __restrict__ ctx)
{
    extern __shared__ float sm[];
    float* Qh = sm;                  // [128][68]
    float* Ql = Qh + 128 * ASTR;
    float* Kh = Ql + 128 * ASTR;     // [64][68]
    float* Kl = Kh + 64 * ASTR;
    float* Vh = Kl + 64 * ASTR;      // [64][68]
    float* Vl = Vh + 64 * ASTR;
    float* Ph = Vl + 64 * ASTR;      // [128][68]
    float* Pl = Ph + 128 * ASTR;

    const int tid = threadIdx.x;
    const int q0 = blockIdx.x * 128;
    const int h  = blockIdx.y;
    const int b  = blockIdx.z;

    const int wid = tid >> 5, lane = tid & 31;
    const int grp = lane >> 2, t4 = lane & 3;
    const int mw = wid * 16;                 // warp's q-row base (local)

    // K/V gmem addressing for the prefetch loads (4 rows per thread chunk)
    const int kv_r = tid >> 4;               // 0..15 -> row group base
    const int kv_c = (tid & 15) * 4;         // 0..60

    // ---- load Q tile (128 x 64), hi/lo split ----
    {
        const float* qbase = qkv + (size_t)(b * SS + q0) * 3 * HIDDEN + h * DH;
#pragma unroll
        for (int u = 0; u < 8; u++) {
            int idx = tid + u * 256;
            int r = idx >> 4, c = (idx & 15) * 4;
            float4 v = *(const float4*)(qbase + (size_t)r * 3 * HIDDEN + c);
            float4 hi, lo;
            split4(v, hi, lo);
            *(float4*)&Qh[r * ASTR + c] = hi;
            *(float4*)&Ql[r * ASTR + c] = lo;
        }
    }

    float out[8][4];
    float mi0 = -1e30f, mi1 = -1e30f, li0 = 0.f, li1 = 0.f;
#pragma unroll
    for (int nt = 0; nt < 8; nt++)
#pragma unroll
        for (int j = 0; j < 4; j++) out[nt][j] = 0.f;

    // ---- prefetch K/V tile 0 into registers ----
    float4 kvr[4], vvr[4];
    {
        const float* kb = qkv + ((size_t)(b * SS) * 3 + 1) * HIDDEN + h * DH;
        const float* vb = kb + HIDDEN;
#pragma unroll
        for (int u = 0; u < 4; u++) {
            int r = kv_r + u * 16;
            kvr[u] = *(const float4*)(kb + (size_t)r * 3 * HIDDEN + kv_c);
            vvr[u] = *(const float4*)(vb + (size_t)r * 3 * HIDDEN + kv_c);
        }
    }

    for (int kt = 0; kt < SS / 64; kt++) {
        // ---- split + store current K/V tile (regs -> smem) ----
#pragma unroll
        for (int u = 0; u < 4; u++) {
            int r = kv_r + u * 16;
            float4 hi, lo;
            split4(kvr[u], hi, lo);
            *(float4*)&Kh[r * ASTR + kv_c] = hi;
            *(float4*)&Kl[r * ASTR + kv_c] = lo;
            split4(vvr[u], hi, lo);
            *(float4*)&Vh[r * ASTR + kv_c] = hi;
            *(float4*)&Vl[r * ASTR + kv_c] = lo;
        }
        __syncthreads();

        // ---- prefetch NEXT tile (latency hidden behind compute below) ----
        if (kt + 1 < SS / 64) {
            const float* kb = qkv + ((size_t)(b * SS + (kt + 1) * 64) * 3 + 1) * HIDDEN + h * DH;
            const float* vb = kb + HIDDEN;
#pragma unroll
            for (int u = 0; u < 4; u++) {
                int r = kv_r + u * 16;
                kvr[u] = *(const float4*)(kb + (size_t)r * 3 * HIDDEN + kv_c);
                vvr[u] = *(const float4*)(vb + (size_t)r * 3 * HIDDEN + kv_c);
            }
        }

        // ---- S = Q @ K^T   (M=16 q, N=64 keys, K=64 d) ----
        float sc[8][4];
#pragma unroll
        for (int nt = 0; nt < 8; nt++)
#pragma unroll
            for (int j = 0; j < 4; j++) sc[nt][j] = 0.f;

#pragma unroll
        for (int k8 = 0; k8 < 64; k8 += 8) {
            float ah[4], al[4];
            int mr = mw + grp;
            ah[0] = Qh[mr * ASTR + k8 + t4];
            ah[1] = Qh[(mr + 8) * ASTR + k8 + t4];
            ah[2] = Qh[mr * ASTR + k8 + t4 + 4];
            ah[3] = Qh[(mr + 8) * ASTR + k8 + t4 + 4];
            al[0] = Ql[mr * ASTR + k8 + t4];
            al[1] = Ql[(mr + 8) * ASTR + k8 + t4];
            al[2] = Ql[mr * ASTR + k8 + t4 + 4];
            al[3] = Ql[(mr + 8) * ASTR + k8 + t4 + 4];
#pragma unroll
            for (int nt = 0; nt < 8; nt++) {
                float bh[2], bl[2];
                int kr = nt * 8 + grp;               // key row
                bh[0] = Kh[kr * ASTR + k8 + t4];
                bh[1] = Kh[kr * ASTR + k8 + t4 + 4];
                bl[0] = Kl[kr * ASTR + k8 + t4];
                bl[1] = Kl[kr * ASTR + k8 + t4 + 4];
                mma3(sc[nt], ah, al, bh, bl);
            }
        }

        // ---- online softmax (rows grp and grp+8 of warp band) ----
        float rm0 = -1e30f, rm1 = -1e30f;
#pragma unroll
        for (int nt = 0; nt < 8; nt++) {
#pragma unroll
            for (int j = 0; j < 4; j++) sc[nt][j] *= 0.125f;
            rm0 = fmaxf(rm0, fmaxf(sc[nt][0], sc[nt][1]));
            rm1 = fmaxf(rm1, fmaxf(sc[nt][2], sc[nt][3]));
        }
#pragma unroll
        for (int off = 1; off < 4; off <<= 1) {
            rm0 = fmaxf(rm0, __shfl_xor_sync(0xffffffffu, rm0, off));
            rm1 = fmaxf(rm1, __shfl_xor_sync(0xffffffffu, rm1, off));
        }
        float mn0 = fmaxf(mi0, rm0), mn1 = fmaxf(mi1, rm1);
        float rs0 = 0.f, rs1 = 0.f;
#pragma unroll
        for (int nt = 0; nt < 8; nt++) {
            sc[nt][0] = __expf(sc[nt][0] - mn0);
            sc[nt][1] = __expf(sc[nt][1] - mn0);
            sc[nt][2] = __expf(sc[nt][2] - mn1);
            sc[nt][3] = __expf(sc[nt][3] - mn1);
            rs0 += sc[nt][0] + sc[nt][1];
            rs1 += sc[nt][2] + sc[nt][3];
        }
#pragma unroll
        for (int off = 1; off < 4; off <<= 1) {
            rs0 += __shfl_xor_sync(0xffffffffu, rs0, off);
            rs1 += __shfl_xor_sync(0xffffffffu, rs1, off);
        }
        float al0 = __expf(mi0 - mn0), al1 = __expf(mi1 - mn1);
        li0 = li0 * al0 + rs0;
        li1 = li1 * al1 + rs1;
        mi0 = mn0; mi1 = mn1;

        // rescale accumulators, stage P (hi/lo) in smem for re-fragmenting
        int pr0 = (mw + grp) * ASTR, pr1 = (mw + grp + 8) * ASTR;
#pragma unroll
        for (int nt = 0; nt < 8; nt++) {
            out[nt][0] *= al0; out[nt][1] *= al0;
            out[nt][2] *= al1; out[nt][3] *= al1;
            int pc = nt * 8 + 2 * t4;
            float h0 = tf32r(sc[nt][0]), h1 = tf32r(sc[nt][1]);
            float h2 = tf32r(sc[nt][2]), h3 = tf32r(sc[nt][3]);
            float2 ph0 = {h0, h1}, ph1 = {h2, h3};
            float2 pl0 = {tf32r(sc[nt][0] - h0), tf32r(sc[nt][1] - h1)};
            float2 pl1 = {tf32r(sc[nt][2] - h2), tf32r(sc[nt][3] - h3)};
            *(float2*)&Ph[pr0 + pc] = ph0;
            *(float2*)&Ph[pr1 + pc] = ph1;
            *(float2*)&Pl[pr0 + pc] = pl0;
            *(float2*)&Pl[pr1 + pc] = pl1;
        }
        __syncwarp();   // warp reads only its own P rows

        // ---- out += P @ V   (M=16 q, N=64 d, K=64 keys) ----
#pragma unroll
        for (int k8 = 0; k8 < 64; k8 += 8) {
            float ah[4], al[4];
            int mr = mw + grp;
            ah[0] = Ph[mr * ASTR + k8 + t4];
            ah[1] = Ph[(mr + 8) * ASTR + k8 + t4];
            ah[2] = Ph[mr * ASTR + k8 + t4 + 4];
            ah[3] = Ph[(mr + 8) * ASTR + k8 + t4 + 4];
            al[0] = Pl[mr * ASTR + k8 + t4];
            al[1] = Pl[(mr + 8) * ASTR + k8 + t4];
            al[2] = Pl[mr * ASTR + k8 + t4 + 4];
            al[3] = Pl[(mr + 8) * ASTR + k8 + t4 + 4];
#pragma unroll
            for (int nt = 0; nt < 8; nt++) {
                float bh[2], bl[2];
                int nc = nt * 8 + grp;               // d column
                bh[0] = Vh[(k8 + t4) * ASTR + nc];
                bh[1] = Vh[(k8 + t4 + 4) * ASTR + nc];
                bl[0] = Vl[(k8 + t4) * ASTR + nc];
                bl[1] = Vl[(k8 + t4 + 4) * ASTR + nc];
                mma3(out[nt], ah, al, bh, bl);
            }
        }
        __syncthreads();   // all reads done before next iteration's stores
    }

    // ---- write ctx ----
    float inv0 = 1.0f / li0, inv1 = 1.0f / li1;
    size_t row0 = (size_t)(b * SS + q0 + mw + grp) * HIDDEN + h * DH;
    size_t row1 = row0 + (size_t)8 * HIDDEN;
#pragma unroll
    for (int nt = 0; nt < 8; nt++) {
        int col = nt * 8 + 2 * t4;
        float2 o0 = {out[nt][0] * inv0, out[nt][1] * inv0};
        float2 o1 = {out[nt][2] * inv1, out[nt][3] * inv1};
        *(float2*)&ctx[row0 + col] = o0;
        *(float2*)&ctx[row1 + col] = o1;
    }
}

// =================================================================
// LayerNorm: one block per row of 1024.  out = LN(x + res) * g + b
// =================================================================
__global__ void __launch_bounds__(256)
ln_kernel(const float* __restrict__ x, const float* __restrict__ res,
          const float* __restrict__ g, const float* __restrict__ beta,
          float* __restrict__ out)
{
    const int row = blockIdx.x;
    const int t = threadIdx.x;

    float4 v = ((const float4*)(x + (size_t)row * HIDDEN))[t];
    if (res) {
        float4 r = ((const float4*)(res + (size_t)row * HIDDEN))[t];
        v.x += r.x; v.y += r.y; v.z += r.z; v.w += r.w;
    }
    float s  = v.x + v.y + v.z + v.w;
    float sq = v.x * v.x + v.y * v.y + v.z * v.z + v.w * v.w;

#pragma unroll
    for (int off = 16; off > 0; off >>= 1) {
        s  += __shfl_xor_sync(0xffffffffu, s,  off);
        sq += __shfl_xor_sync(0xffffffffu, sq, off);
    }
    __shared__ float ss[8], ssq[8];
    __shared__ float smean, srstd;
    int warp = t >> 5, lane = t & 31;
    if (lane == 0) { ss[warp] = s; ssq[warp] = sq; }
    __syncthreads();
    if (t == 0) {
        float S = 0.f, Q = 0.f;
#pragma unroll
        for (int i = 0; i < 8; i++) { S += ss[i]; Q += ssq[i]; }
        float mean = S * (1.0f / HIDDEN);
        float var  = Q * (1.0f / HIDDEN) - mean * mean;
        smean = mean;
        srstd = rsqrtf(var + 1e-5f);
    }
    __syncthreads();
    float mean = smean, rstd = srstd;

    float4 gg = ((const float4*)g)[t];
    float4 bb = ((const float4*)beta)[t];
    float4 o;
    o.x = (v.x - mean) * rstd * gg.x + bb.x;
    o.y = (v.y - mean) * rstd * gg.y + bb.y;
    o.z = (v.z - mean) * rstd * gg.z + bb.z;
    o.w = (v.w - mean) * rstd * gg.w + bb.w;
    ((float4*)(out + (size_t)row * HIDDEN))[t] = o;
}

// =================================================================
// launch
// =================================================================
extern "C" void kernel_launch(void* const* d_in, const int* in_sizes, int n_in,
                              void* d_out, int out_size)
{
    const float* x     = (const float*)d_in[0];
    const float* in_W  = (const float*)d_in[1];
    const float* in_b  = (const float*)d_in[2];
    const float* qkv_W = (const float*)d_in[3];
    const float* qkv_b = (const float*)d_in[4];
    const float* out_W = (const float*)d_in[5];
    const float* out_b = (const float*)d_in[6];
    const float* ln1_g = (const float*)d_in[7];
    const float* ln1_b = (const float*)d_in[8];
    const float* ln2_g = (const float*)d_in[9];
    const float* ln2_b = (const float*)d_in[10];
    const float* ff1_W = (const float*)d_in[11];
    const float* ff1_b = (const float*)d_in[12];
    const float* ff2_W = (const float*)d_in[13];
    const float* ff2_b = (const float*)d_in[14];
    const float* fin_g = (const float*)d_in[15];
    const float* fin_b = (const float*)d_in[16];
    const float* op_W  = (const float*)d_in[17];
    const float* op_b  = (const float*)d_in[18];
    float* out = (float*)d_out;

    float *h, *qkv, *ctx, *y, *ff;
    cudaGetSymbolAddress((void**)&h,   g_h);
    cudaGetSymbolAddress((void**)&qkv, g_qkv);
    cudaGetSymbolAddress((void**)&ctx, g_ctx);
    cudaGetSymbolAddress((void**)&y,   g_y);
    cudaGetSymbolAddress((void**)&ff,  g_ff);

    cudaFuncSetAttribute(attn_tc, cudaFuncAttributeMaxDynamicSharedMemorySize,
                         (int)ATTN_SMEM);
    cudaFuncSetAttribute(gemm_tc<0>, cudaFuncAttributeMaxDynamicSharedMemorySize,
                         (int)GEMM_SMEM);
    cudaFuncSetAttribute(gemm_tc<1>, cudaFuncAttributeMaxDynamicSharedMemorySize,
                         (int)GEMM_SMEM);
    cudaFuncSetAttribute(gemm_tc<2>, cudaFuncAttributeMaxDynamicSharedMemorySize,
                         (int)GEMM_SMEM);

    const int M = M_ROWS;
    dim3 blk(256);

    // input projection + sqrt(H)*scale + positional encoding
    gemm_tc<2><<<dim3(HIDDEN / 128, M / 128), blk, GEMM_SMEM>>>(x, in_W, in_b, h, M, HIDDEN, IN_DIM);

    for (int l = 0; l < LAYERS; l++) {
        const float* qW  = qkv_W + (size_t)l * HIDDEN * 3 * HIDDEN;
        const float* qb  = qkv_b + (size_t)l * 3 * HIDDEN;
        const float* oW  = out_W + (size_t)l * HIDDEN * HIDDEN;
        const float* ob  = out_b + (size_t)l * HIDDEN;
        const float* f1W = ff1_W + (size_t)l * HIDDEN * FF_DIM;
        const float* f1b = ff1_b + (size_t)l * FF_DIM;
        const float* f2W = ff2_W + (size_t)l * FF_DIM * HIDDEN;
        const float* f2b = ff2_b + (size_t)l * HIDDEN;

        gemm_tc<0><<<dim3(3 * HIDDEN / 128, M / 128), blk, GEMM_SMEM>>>(h, qW, qb, qkv, M, 3 * HIDDEN, HIDDEN);
        attn_tc<<<dim3(SS / 128, HEADS, BB), blk, ATTN_SMEM>>>(qkv, ctx);
        gemm_tc<0><<<dim3(HIDDEN / 128, M / 128), blk, GEMM_SMEM>>>(ctx, oW, ob, y, M, HIDDEN, HIDDEN);
        ln_kernel<<<M, blk>>>(h, y, ln1_g + l * HIDDEN, ln1_b + l * HIDDEN, h);
        gemm_tc<1><<<dim3(FF_DIM / 128, M / 128), blk, GEMM_SMEM>>>(h, f1W, f1b, ff, M, FF_DIM, HIDDEN);
        gemm_tc<0><<<dim3(HIDDEN / 128, M / 128), blk, GEMM_SMEM>>>(ff, f2W, f2b, y, M, HIDDEN, FF_DIM);
        ln_kernel<<<M, blk>>>(h, y, ln2_g + l * HIDDEN, ln2_b + l * HIDDEN, h);
    }

    // final LN then output projection
    ln_kernel<<<M, blk>>>(h, nullptr, fin_g, fin_b, ctx);
    gemm_tc<0><<<dim3(OUT_DIM / 128, M / 128), blk, GEMM_SMEM>>>(ctx, op_W, op_b, out, M, OUT_DIM, HIDDEN);
}

// round 11
// speedup vs baseline: 1.3725x; 1.3725x over previous
#include <cuda_runtime.h>
#include <cuda_bf16.h>
#include <math.h>
#include <stdint.h>

// ---------------- problem constants ----------------
#define BB      4
#define SS      2048
#define HIDDEN  1024
#define HEADS   16
#define DH      64
#define LAYERS  4
#define IN_DIM  512
#define OUT_DIM 1024
#define FF_DIM  4096
#define M_ROWS  (BB * SS)          // 8192

// ---------------- scratch (no allocation allowed) ----------------
__device__ float g_h  [(size_t)M_ROWS * HIDDEN];
__device__ float g_qkv[(size_t)M_ROWS * 3 * HIDDEN];
__device__ float g_ctx[(size_t)M_ROWS * HIDDEN];
__device__ float g_y  [(size_t)M_ROWS * HIDDEN];
__device__ float g_ff [(size_t)M_ROWS * FF_DIM];

// pre-split weight buffers (hi/lo), one big arena each
#define W_TOTAL 51904512   // in(0.5M)+qkv(12.6M)+out(4.2M)+ff1(16.8M)+ff2(16.8M)+op(1M)
__device__ float g_wh[(size_t)W_TOTAL];
__device__ float g_wl[(size_t)W_TOTAL];
// pre-split activation buffers (max size = ff: 8192*4096)
__device__ float g_ah[(size_t)M_ROWS * FF_DIM];
__device__ float g_al[(size_t)M_ROWS * FF_DIM];

// ---------------- tf32 helpers ----------------
__device__ __forceinline__ float tf32r(float x) {
    uint32_t u;
    asm("cvt.rna.tf32.f32 %0, %1;" : "=r"(u) : "f"(x));
    return __uint_as_float(u);
}
__device__ __forceinline__ void split4(float4 v, float4& hi, float4& lo) {
    hi.x = tf32r(v.x); lo.x = tf32r(v.x - hi.x);
    hi.y = tf32r(v.y); lo.y = tf32r(v.y - hi.y);
    hi.z = tf32r(v.z); lo.z = tf32r(v.z - hi.z);
    hi.w = tf32r(v.w); lo.w = tf32r(v.w - hi.w);
}
// D = A(16x8,row) * B(8x8,col) + D, tf32 inputs, f32 accum
__device__ __forceinline__ void mma_tf32(float* c, const float* a, const float* b) {
    asm volatile(
        "mma.sync.aligned.m16n8k8.row.col.f32.tf32.tf32.f32 "
        "{%0,%1,%2,%3}, {%4,%5,%6,%7}, {%8,%9}, {%0,%1,%2,%3};\n"
        : "+f"(c[0]), "+f"(c[1]), "+f"(c[2]), "+f"(c[3])
        : "r"(__float_as_uint(a[0])), "r"(__float_as_uint(a[1])),
          "r"(__float_as_uint(a[2])), "r"(__float_as_uint(a[3])),
          "r"(__float_as_uint(b[0])), "r"(__float_as_uint(b[1])));
}
// 3xTF32: c += Ahi*Bhi + Ahi*Blo + Alo*Bhi
__device__ __forceinline__ void mma3(float* c, const float* ah, const float* al,
                                     const float* bh, const float* bl) {
    mma_tf32(c, ah, bl);
    mma_tf32(c, al, bh);
    mma_tf32(c, ah, bh);
}

__device__ __forceinline__ uint32_t smem_u32(const void* p) {
    uint32_t a;
    asm("{ .reg .u64 t; cvta.to.shared.u64 t, %1; cvt.u32.u64 %0, t; }"
        : "=r"(a) : "l"(p));
    return a;
}
#define CP16(dst_u32, src_ptr) \
    asm volatile("cp.async.cg.shared.global [%0], [%1], 16;" :: "r"(dst_u32), "l"(src_ptr))
#define CP_COMMIT()  asm volatile("cp.async.commit_group;")
#define CP_WAIT1()   asm volatile("cp.async.wait_group 1;")
#define CP_WAIT0()   asm volatile("cp.async.wait_group 0;")

// =================================================================
// Elementwise hi/lo split: n4 float4 elements
// =================================================================
__global__ void __launch_bounds__(256)
split_kernel(const float* __restrict__ src, float* __restrict__ hi,
             float* __restrict__ lo, int n4)
{
    int i = blockIdx.x * blockDim.x + threadIdx.x;
    if (i < n4) {
        float4 v = ((const float4*)src)[i];
        float4 h, l;
        split4(v, h, l);
        ((float4*)hi)[i] = h;
        ((float4*)lo)[i] = l;
    }
}

// =================================================================
// Tensor-core GEMM (3xTF32), pre-split inputs, cp.async 3-stage.
// C[M,N] = (Ah+Al)[M,K] @ (Bh+Bl)[K,N] + bias
// EPI: 0 = bias, 1 = bias+relu, 2 = bias then *32 + posenc
// BM=BN=128, BK=16, 256 threads (8 warps, 2x4), warp tile 64x32.
// smem per stage: Ah[128][20], Al[128][20], Bh[16][132], Bl[16][132]
// =================================================================
#define AS_F  (128 * 20)     // 2560 floats
#define BS_F  (16 * 132)     // 2112 floats
#define STG_F (2 * AS_F + 2 * BS_F)                 // 9344 floats per stage
#define GEMM_SMEM (3 * STG_F * sizeof(float))       // 112128 B

template<int EPI>
__global__ void __launch_bounds__(256, 2)
gemm_tc(const float* __restrict__ Ah, const float* __restrict__ Al,
        const float* __restrict__ Bh, const float* __restrict__ Bl,
        const float* __restrict__ bias, float* __restrict__ C,
        int M, int N, int K)
{
    extern __shared__ __align__(16) float smp[];
    const uint32_t sbase = smem_u32(smp);

    const int tid = threadIdx.x;
    const int cb = blockIdx.x * 128;
    const int rb = blockIdx.y * 128;

    // cp.async addressing
    const int arow = tid >> 1;           // 0..127
    const int ac0  = (tid & 1) * 8;      // 0 or 8 (two 16B chunks: ac0, ac0+4)
    const int br0  = tid >> 5;           // 0..7   (rows br0 and br0+8)
    const int bc   = (tid & 31) * 4;     // 0..124

    const float* gAh = Ah + (size_t)(rb + arow) * K + ac0;
    const float* gAl = Al + (size_t)(rb + arow) * K + ac0;
    const float* gBh = Bh + (size_t)br0 * N + cb + bc;
    const float* gBl = Bl + (size_t)br0 * N + cb + bc;

    const int wid = tid >> 5, lane = tid & 31;
    const int grp = lane >> 2, t4 = lane & 3;
    const int m0 = (wid >> 2) * 64;      // 0 or 64
    const int n0 = (wid & 3) * 32;       // 0,32,64,96

    // per-thread smem write offsets (bytes) within a stage
    const uint32_t oAh = (uint32_t)(arow * 20 + ac0) * 4;
    const uint32_t oAl = oAh + AS_F * 4;
    const uint32_t oBh = (uint32_t)(2 * AS_F + br0 * 132 + bc) * 4;
    const uint32_t oBl = oBh + BS_F * 4;

    auto issue_stage = [&](int s, int k0) {
        uint32_t sb = sbase + (uint32_t)(s * STG_F) * 4;
        const float* a_h = gAh + k0;
        const float* a_l = gAl + k0;
        CP16(sb + oAh,      a_h);
        CP16(sb + oAh + 16, a_h + 4);
        CP16(sb + oAl,      a_l);
        CP16(sb + oAl + 16, a_l + 4);
        const float* b_h = gBh + (size_t)k0 * N;
        const float* b_l = gBl + (size_t)k0 * N;
        CP16(sb + oBh, b_h);
        CP16(sb + oBh + 8 * 132 * 4, b_h + (size_t)8 * N);
        CP16(sb + oBl, b_l);
        CP16(sb + oBl + 8 * 132 * 4, b_l + (size_t)8 * N);
        CP_COMMIT();
    };

    float acc[4][4][4];
#pragma unroll
    for (int mt = 0; mt < 4; mt++)
#pragma unroll
        for (int nt = 0; nt < 4; nt++)
#pragma unroll
            for (int j = 0; j < 4; j++) acc[mt][nt][j] = 0.f;

    const int ntile = K / 16;
    issue_stage(0, 0);
    if (ntile > 1) issue_stage(1, 16);

    for (int i = 0; i < ntile; i++) {
        if (i + 1 < ntile) { CP_WAIT1(); } else { CP_WAIT0(); }
        __syncthreads();

        if (i + 2 < ntile) issue_stage((i + 2) % 3, (i + 2) * 16);

        const float* Ahs = smp + (i % 3) * STG_F;
        const float* Als = Ahs + AS_F;
        const float* Bhs = Als + AS_F;
        const float* Bls = Bhs + BS_F;

#pragma unroll
        for (int k8 = 0; k8 < 16; k8 += 8) {
            float ah[4][4], al[4][4], bh[4][2], bl[4][2];
#pragma unroll
            for (int mt = 0; mt < 4; mt++) {
                int mr = m0 + mt * 16 + grp;
                ah[mt][0] = Ahs[mr * 20 + k8 + t4];
                ah[mt][1] = Ahs[(mr + 8) * 20 + k8 + t4];
                ah[mt][2] = Ahs[mr * 20 + k8 + t4 + 4];
                ah[mt][3] = Ahs[(mr + 8) * 20 + k8 + t4 + 4];
                al[mt][0] = Als[mr * 20 + k8 + t4];
                al[mt][1] = Als[(mr + 8) * 20 + k8 + t4];
                al[mt][2] = Als[mr * 20 + k8 + t4 + 4];
                al[mt][3] = Als[(mr + 8) * 20 + k8 + t4 + 4];
            }
#pragma unroll
            for (int nt = 0; nt < 4; nt++) {
                int nc = n0 + nt * 8 + grp;
                bh[nt][0] = Bhs[(k8 + t4) * 132 + nc];
                bh[nt][1] = Bhs[(k8 + t4 + 4) * 132 + nc];
                bl[nt][0] = Bls[(k8 + t4) * 132 + nc];
                bl[nt][1] = Bls[(k8 + t4 + 4) * 132 + nc];
            }
#pragma unroll
            for (int mt = 0; mt < 4; mt++)
#pragma unroll
                for (int nt = 0; nt < 4; nt++)
                    mma3(acc[mt][nt], ah[mt], al[mt], bh[nt], bl[nt]);
        }
        __syncthreads();   // stage (i%3) free for reuse two iterations later
    }

    // ---- epilogue ----
#pragma unroll
    for (int mt = 0; mt < 4; mt++) {
#pragma unroll
        for (int nt = 0; nt < 4; nt++) {
            int col = cb + n0 + nt * 8 + 2 * t4;
            float b0 = bias[col], b1 = bias[col + 1];
#pragma unroll
            for (int half = 0; half < 2; half++) {
                int row = rb + m0 + mt * 16 + grp + half * 8;
                float c0 = acc[mt][nt][half * 2 + 0] + b0;
                float c1 = acc[mt][nt][half * 2 + 1] + b1;
                if (EPI == 1) { c0 = fmaxf(c0, 0.f); c1 = fmaxf(c1, 0.f); }
                if (EPI == 2) {
                    int srow = row & (SS - 1);
                    float f0 = expf(-9.210340371976184f * (float)(col & ~1) * (1.0f / 1024.0f));
                    float f1 = expf(-9.210340371976184f * (float)((col + 1) & ~1) * (1.0f / 1024.0f));
                    float a0 = (float)srow * f0, a1 = (float)srow * f1;
                    float p0 = (col & 1) ? cosf(a0) : sinf(a0);
                    float p1 = ((col + 1) & 1) ? cosf(a1) : sinf(a1);
                    c0 = c0 * 32.0f + p0;
                    c1 = c1 * 32.0f + p1;
                }
                float2 o = {c0, c1};
                *(float2*)(C + (size_t)row * N + col) = o;
            }
        }
    }
}

// =================================================================
// Flash attention, 3xTF32 tensor cores, register-prefetched K/V.
// Block = (b, h, 128 q-rows), 256 threads = 8 warps, warp owns 16 q rows.
// =================================================================
#define ASTR 68
#define ATTN_SMEM ((2 * 128 * ASTR + 2 * 64 * ASTR + 2 * 64 * ASTR + 2 * 128 * ASTR) * sizeof(float))  // 208896

__global__ void __launch_bounds__(256)
attn_tc(const float* __restrict__ qkv, float* __restrict__ ctx)
{
    extern __shared__ float sm[];
    float* Qh = sm;                  // [128][68]
    float* Ql = Qh + 128 * ASTR;
    float* Kh = Ql + 128 * ASTR;     // [64][68]
    float* Kl = Kh + 64 * ASTR;
    float* Vh = Kl + 64 * ASTR;      // [64][68]
    float* Vl = Vh + 64 * ASTR;
    float* Ph = Vl + 64 * ASTR;      // [128][68]
    float* Pl = Ph + 128 * ASTR;

    const int tid = threadIdx.x;
    const int q0 = blockIdx.x * 128;
    const int h  = blockIdx.y;
    const int b  = blockIdx.z;

    const int wid = tid >> 5, lane = tid & 31;
    const int grp = lane >> 2, t4 = lane & 3;
    const int mw = wid * 16;                 // warp's q-row base (local)

    const int kv_r = tid >> 4;               // 0..15
    const int kv_c = (tid & 15) * 4;         // 0..60

    // ---- load Q tile (128 x 64), hi/lo split ----
    {
        const float* qbase = qkv + (size_t)(b * SS + q0) * 3 * HIDDEN + h * DH;
#pragma unroll
        for (int u = 0; u < 8; u++) {
            int idx = tid + u * 256;
            int r = idx >> 4, c = (idx & 15) * 4;
            float4 v = *(const float4*)(qbase + (size_t)r * 3 * HIDDEN + c);
            float4 hi, lo;
            split4(v, hi, lo);
            *(float4*)&Qh[r * ASTR + c] = hi;
            *(float4*)&Ql[r * ASTR + c] = lo;
        }
    }

    float out[8][4];
    float mi0 = -1e30f, mi1 = -1e30f, li0 = 0.f, li1 = 0.f;
#pragma unroll
    for (int nt = 0; nt < 8; nt++)
#pragma unroll
        for (int j = 0; j < 4; j++) out[nt][j] = 0.f;

    // ---- prefetch K/V tile 0 into registers ----
    float4 kvr[4], vvr[4];
    {
        const float* kb = qkv + ((size_t)(b * SS) * 3 + 1) * HIDDEN + h * DH;
        const float* vb = kb + HIDDEN;
#pragma unroll
        for (int u = 0; u < 4; u++) {
            int r = kv_r + u * 16;
            kvr[u] = *(const float4*)(kb + (size_t)r * 3 * HIDDEN + kv_c);
            vvr[u] = *(const float4*)(vb + (size_t)r * 3 * HIDDEN + kv_c);
        }
    }

    for (int kt = 0; kt < SS / 64; kt++) {
        // ---- split + store current K/V tile (regs -> smem) ----
#pragma unroll
        for (int u = 0; u < 4; u++) {
            int r = kv_r + u * 16;
            float4 hi, lo;
            split4(kvr[u], hi, lo);
            *(float4*)&Kh[r * ASTR + kv_c] = hi;
            *(float4*)&Kl[r * ASTR + kv_c] = lo;
            split4(vvr[u], hi, lo);
            *(float4*)&Vh[r * ASTR + kv_c] = hi;
            *(float4*)&Vl[r * ASTR + kv_c] = lo;
        }
        __syncthreads();

        // ---- prefetch NEXT tile (hidden behind compute) ----
        if (kt + 1 < SS / 64) {
            const float* kb = qkv + ((size_t)(b * SS + (kt + 1) * 64) * 3 + 1) * HIDDEN + h * DH;
            const float* vb = kb + HIDDEN;
#pragma unroll
            for (int u = 0; u < 4; u++) {
                int r = kv_r + u * 16;
                kvr[u] = *(const float4*)(kb + (size_t)r * 3 * HIDDEN + kv_c);
                vvr[u] = *(const float4*)(vb + (size_t)r * 3 * HIDDEN + kv_c);
            }
        }

        // ---- S = Q @ K^T ----
        float sc[8][4];
#pragma unroll
        for (int nt = 0; nt < 8; nt++)
#pragma unroll
            for (int j = 0; j < 4; j++) sc[nt][j] = 0.f;

#pragma unroll
        for (int k8 = 0; k8 < 64; k8 += 8) {
            float ah[4], al[4];
            int mr = mw + grp;
            ah[0] = Qh[mr * ASTR + k8 + t4];
            ah[1] = Qh[(mr + 8) * ASTR + k8 + t4];
            ah[2] = Qh[mr * ASTR + k8 + t4 + 4];
            ah[3] = Qh[(mr + 8) * ASTR + k8 + t4 + 4];
            al[0] = Ql[mr * ASTR + k8 + t4];
            al[1] = Ql[(mr + 8) * ASTR + k8 + t4];
            al[2] = Ql[mr * ASTR + k8 + t4 + 4];
            al[3] = Ql[(mr + 8) * ASTR + k8 + t4 + 4];
#pragma unroll
            for (int nt = 0; nt < 8; nt++) {
                float bh[2], bl[2];
                int kr = nt * 8 + grp;
                bh[0] = Kh[kr * ASTR + k8 + t4];
                bh[1] = Kh[kr * ASTR + k8 + t4 + 4];
                bl[0] = Kl[kr * ASTR + k8 + t4];
                bl[1] = Kl[kr * ASTR + k8 + t4 + 4];
                mma3(sc[nt], ah, al, bh, bl);
            }
        }

        // ---- online softmax ----
        float rm0 = -1e30f, rm1 = -1e30f;
#pragma unroll
        for (int nt = 0; nt < 8; nt++) {
#pragma unroll
            for (int j = 0; j < 4; j++) sc[nt][j] *= 0.125f;
            rm0 = fmaxf(rm0, fmaxf(sc[nt][0], sc[nt][1]));
            rm1 = fmaxf(rm1, fmaxf(sc[nt][2], sc[nt][3]));
        }
#pragma unroll
        for (int off = 1; off < 4; off <<= 1) {
            rm0 = fmaxf(rm0, __shfl_xor_sync(0xffffffffu, rm0, off));
            rm1 = fmaxf(rm1, __shfl_xor_sync(0xffffffffu, rm1, off));
        }
        float mn0 = fmaxf(mi0, rm0), mn1 = fmaxf(mi1, rm1);
        float rs0 = 0.f, rs1 = 0.f;
#pragma unroll
        for (int nt = 0; nt < 8; nt++) {
            sc[nt][0] = __expf(sc[nt][0] - mn0);
            sc[nt][1] = __expf(sc[nt][1] - mn0);
            sc[nt][2] = __expf(sc[nt][2] - mn1);
            sc[nt][3] = __expf(sc[nt][3] - mn1);
            rs0 += sc[nt][0] + sc[nt][1];
            rs1 += sc[nt][2] + sc[nt][3];
        }
#pragma unroll
        for (int off = 1; off < 4; off <<= 1) {
            rs0 += __shfl_xor_sync(0xffffffffu, rs0, off);
            rs1 += __shfl_xor_sync(0xffffffffu, rs1, off);
        }
        float al0 = __expf(mi0 - mn0), al1 = __expf(mi1 - mn1);
        li0 = li0 * al0 + rs0;
        li1 = li1 * al1 + rs1;
        mi0 = mn0; mi1 = mn1;

        int pr0 = (mw + grp) * ASTR, pr1 = (mw + grp + 8) * ASTR;
#pragma unroll
        for (int nt = 0; nt < 8; nt++) {
            out[nt][0] *= al0; out[nt][1] *= al0;
            out[nt][2] *= al1; out[nt][3] *= al1;
            int pc = nt * 8 + 2 * t4;
            float h0 = tf32r(sc[nt][0]), h1 = tf32r(sc[nt][1]);
            float h2 = tf32r(sc[nt][2]), h3 = tf32r(sc[nt][3]);
            float2 ph0 = {h0, h1}, ph1 = {h2, h3};
            float2 pl0 = {tf32r(sc[nt][0] - h0), tf32r(sc[nt][1] - h1)};
            float2 pl1 = {tf32r(sc[nt][2] - h2), tf32r(sc[nt][3] - h3)};
            *(float2*)&Ph[pr0 + pc] = ph0;
            *(float2*)&Ph[pr1 + pc] = ph1;
            *(float2*)&Pl[pr0 + pc] = pl0;
            *(float2*)&Pl[pr1 + pc] = pl1;
        }
        __syncwarp();

        // ---- out += P @ V ----
#pragma unroll
        for (int k8 = 0; k8 < 64; k8 += 8) {
            float ah[4], al[4];
            int mr = mw + grp;
            ah[0] = Ph[mr * ASTR + k8 + t4];
            ah[1] = Ph[(mr + 8) * ASTR + k8 + t4];
            ah[2] = Ph[mr * ASTR + k8 + t4 + 4];
            ah[3] = Ph[(mr + 8) * ASTR + k8 + t4 + 4];
            al[0] = Pl[mr * ASTR + k8 + t4];
            al[1] = Pl[(mr + 8) * ASTR + k8 + t4];
            al[2] = Pl[mr * ASTR + k8 + t4 + 4];
            al[3] = Pl[(mr + 8) * ASTR + k8 + t4 + 4];
#pragma unroll
            for (int nt = 0; nt < 8; nt++) {
                float bh[2], bl[2];
                int nc = nt * 8 + grp;
                bh[0] = Vh[(k8 + t4) * ASTR + nc];
                bh[1] = Vh[(k8 + t4 + 4) * ASTR + nc];
                bl[0] = Vl[(k8 + t4) * ASTR + nc];
                bl[1] = Vl[(k8 + t4 + 4) * ASTR + nc];
                mma3(out[nt], ah, al, bh, bl);
            }
        }
        __syncthreads();
    }

    // ---- write ctx ----
    float inv0 = 1.0f / li0, inv1 = 1.0f / li1;
    size_t row0 = (size_t)(b * SS + q0 + mw + grp) * HIDDEN + h * DH;
    size_t row1 = row0 + (size_t)8 * HIDDEN;
#pragma unroll
    for (int nt = 0; nt < 8; nt++) {
        int col = nt * 8 + 2 * t4;
        float2 o0 = {out[nt][0] * inv0, out[nt][1] * inv0};
        float2 o1 = {out[nt][2] * inv1, out[nt][3] * inv1};
        *(float2*)&ctx[row0 + col] = o0;
        *(float2*)&ctx[row1 + col] = o1;
    }
}

// =================================================================
// LayerNorm: one block per row of 1024.  out = LN(x + res) * g + b
// =================================================================
__global__ void __launch_bounds__(256)
ln_kernel(const float* __restrict__ x, const float* __restrict__ res,
          const float* __restrict__ g, const float* __restrict__ beta,
          float* __restrict__ out)
{
    const int row = blockIdx.x;
    const int t = threadIdx.x;

    float4 v = ((const float4*)(x + (size_t)row * HIDDEN))[t];
    if (res) {
        float4 r = ((const float4*)(res + (size_t)row * HIDDEN))[t];
        v.x += r.x; v.y += r.y; v.z += r.z; v.w += r.w;
    }
    float s  = v.x + v.y + v.z + v.w;
    float sq = v.x * v.x + v.y * v.y + v.z * v.z + v.w * v.w;

#pragma unroll
    for (int off = 16; off > 0; off >>= 1) {
        s  += __shfl_xor_sync(0xffffffffu, s,  off);
        sq += __shfl_xor_sync(0xffffffffu, sq, off);
    }
    __shared__ float ss[8], ssq[8];
    __shared__ float smean, srstd;
    int warp = t >> 5, lane = t & 31;
    if (lane == 0) { ss[warp] = s; ssq[warp] = sq; }
    __syncthreads();
    if (t == 0) {
        float S = 0.f, Q = 0.f;
#pragma unroll
        for (int i = 0; i < 8; i++) { S += ss[i]; Q += ssq[i]; }
        float mean = S * (1.0f / HIDDEN);
        float var  = Q * (1.0f / HIDDEN) - mean * mean;
        smean = mean;
        srstd = rsqrtf(var + 1e-5f);
    }
    __syncthreads();
    float mean = smean, rstd = srstd;

    float4 gg = ((const float4*)g)[t];
    float4 bb = ((const float4*)beta)[t];
    float4 o;
    o.x = (v.x - mean) * rstd * gg.x + bb.x;
    o.y = (v.y - mean) * rstd * gg.y + bb.y;
    o.z = (v.z - mean) * rstd * gg.z + bb.z;
    o.w = (v.w - mean) * rstd * gg.w + bb.w;
    ((float4*)(out + (size_t)row * HIDDEN))[t] = o;
}

// =================================================================
// launch
// =================================================================
extern "C" void kernel_launch(void* const* d_in, const int* in_sizes, int n_in,
                              void* d_out, int out_size)
{
    const float* x     = (const float*)d_in[0];
    const float* in_W  = (const float*)d_in[1];
    const float* in_b  = (const float*)d_in[2];
    const float* qkv_W = (const float*)d_in[3];
    const float* qkv_b = (const float*)d_in[4];
    const float* out_W = (const float*)d_in[5];
    const float* out_b = (const float*)d_in[6];
    const float* ln1_g = (const float*)d_in[7];
    const float* ln1_b = (const float*)d_in[8];
    const float* ln2_g = (const float*)d_in[9];
    const float* ln2_b = (const float*)d_in[10];
    const float* ff1_W = (const float*)d_in[11];
    const float* ff1_b = (const float*)d_in[12];
    const float* ff2_W = (const float*)d_in[13];
    const float* ff2_b = (const float*)d_in[14];
    const float* fin_g = (const float*)d_in[15];
    const float* fin_b = (const float*)d_in[16];
    const float* op_W  = (const float*)d_in[17];
    const float* op_b  = (const float*)d_in[18];
    float* out = (float*)d_out;

    float *h, *qkv, *ctx, *y, *ff, *wh, *wl, *ah, *al;
    cudaGetSymbolAddress((void**)&h,   g_h);
    cudaGetSymbolAddress((void**)&qkv, g_qkv);
    cudaGetSymbolAddress((void**)&ctx, g_ctx);
    cudaGetSymbolAddress((void**)&y,   g_y);
    cudaGetSymbolAddress((void**)&ff,  g_ff);
    cudaGetSymbolAddress((void**)&wh,  g_wh);
    cudaGetSymbolAddress((void**)&wl,  g_wl);
    cudaGetSymbolAddress((void**)&ah,  g_ah);
    cudaGetSymbolAddress((void**)&al,  g_al);

    cudaFuncSetAttribute(attn_tc, cudaFuncAttributeMaxDynamicSharedMemorySize,
                         (int)ATTN_SMEM);
    cudaFuncSetAttribute(gemm_tc<0>, cudaFuncAttributeMaxDynamicSharedMemorySize,
                         (int)GEMM_SMEM);
    cudaFuncSetAttribute(gemm_tc<1>, cudaFuncAttributeMaxDynamicSharedMemorySize,
                         (int)GEMM_SMEM);
    cudaFuncSetAttribute(gemm_tc<2>, cudaFuncAttributeMaxDynamicSharedMemorySize,
                         (int)GEMM_SMEM);

    const int M = M_ROWS;
    dim3 blk(256);

    // weight arena offsets (floats)
    const size_t ofs_in  = 0;
    const size_t ofs_qkv = ofs_in  + (size_t)IN_DIM * HIDDEN;             // 524288
    const size_t ofs_out = ofs_qkv + (size_t)LAYERS * HIDDEN * 3 * HIDDEN;
    const size_t ofs_ff1 = ofs_out + (size_t)LAYERS * HIDDEN * HIDDEN;
    const size_t ofs_ff2 = ofs_ff1 + (size_t)LAYERS * HIDDEN * FF_DIM;
    const size_t ofs_op  = ofs_ff2 + (size_t)LAYERS * FF_DIM * HIDDEN;

    auto split = [&](const float* src, float* dh, float* dl, size_t n) {
        int n4 = (int)(n / 4);
        split_kernel<<<(n4 + 255) / 256, 256>>>(src, dh, dl, n4);
    };

    // ---- pre-split all weights ----
    split(in_W,  wh + ofs_in,  wl + ofs_in,  (size_t)IN_DIM * HIDDEN);
    split(qkv_W, wh + ofs_qkv, wl + ofs_qkv, (size_t)LAYERS * HIDDEN * 3 * HIDDEN);
    split(out_W, wh + ofs_out, wl + ofs_out, (size_t)LAYERS * HIDDEN * HIDDEN);
    split(ff1_W, wh + ofs_ff1, wl + ofs_ff1, (size_t)LAYERS * HIDDEN * FF_DIM);
    split(ff2_W, wh + ofs_ff2, wl + ofs_ff2, (size_t)LAYERS * FF_DIM * HIDDEN);
    split(op_W,  wh + ofs_op,  wl + ofs_op,  (size_t)HIDDEN * OUT_DIM);

    // ---- input projection + posenc ----
    split(x, ah, al, (size_t)M * IN_DIM);
    gemm_tc<2><<<dim3(HIDDEN / 128, M / 128), blk, GEMM_SMEM>>>(
        ah, al, wh + ofs_in, wl + ofs_in, in_b, h, M, HIDDEN, IN_DIM);

    for (int l = 0; l < LAYERS; l++) {
        const float* qb  = qkv_b + (size_t)l * 3 * HIDDEN;
        const float* ob  = out_b + (size_t)l * HIDDEN;
        const float* f1b = ff1_b + (size_t)l * FF_DIM;
        const float* f2b = ff2_b + (size_t)l * HIDDEN;
        size_t wq  = ofs_qkv + (size_t)l * HIDDEN * 3 * HIDDEN;
        size_t wo  = ofs_out + (size_t)l * HIDDEN * HIDDEN;
        size_t wf1 = ofs_ff1 + (size_t)l * HIDDEN * FF_DIM;
        size_t wf2 = ofs_ff2 + (size_t)l * FF_DIM * HIDDEN;

        split(h, ah, al, (size_t)M * HIDDEN);
        gemm_tc<0><<<dim3(3 * HIDDEN / 128, M / 128), blk, GEMM_SMEM>>>(
            ah, al, wh + wq, wl + wq, qb, qkv, M, 3 * HIDDEN, HIDDEN);
        attn_tc<<<dim3(SS / 128, HEADS, BB), blk, ATTN_SMEM>>>(qkv, ctx);
        split(ctx, ah, al, (size_t)M * HIDDEN);
        gemm_tc<0><<<dim3(HIDDEN / 128, M / 128), blk, GEMM_SMEM>>>(
            ah, al, wh + wo, wl + wo, ob, y, M, HIDDEN, HIDDEN);
        ln_kernel<<<M, blk>>>(h, y, ln1_g + l * HIDDEN, ln1_b + l * HIDDEN, h);
        split(h, ah, al, (size_t)M * HIDDEN);
        gemm_tc<1><<<dim3(FF_DIM / 128, M / 128), blk, GEMM_SMEM>>>(
            ah, al, wh + wf1, wl + wf1, f1b, ff, M, FF_DIM, HIDDEN);
        split(ff, ah, al, (size_t)M * FF_DIM);
        gemm_tc<0><<<dim3(HIDDEN / 128, M / 128), blk, GEMM_SMEM>>>(
            ah, al, wh + wf2, wl + wf2, f2b, y, M, HIDDEN, FF_DIM);
        ln_kernel<<<M, blk>>>(h, y, ln2_g + l * HIDDEN, ln2_b + l * HIDDEN, h);
    }

    // final LN then output projection
    ln_kernel<<<M, blk>>>(h, nullptr, fin_g, fin_b, ctx);
    split(ctx, ah, al, (size_t)M * HIDDEN);
    gemm_tc<0><<<dim3(OUT_DIM / 128, M / 128), blk, GEMM_SMEM>>>(
        ah, al, wh + ofs_op, wl + ofs_op, op_b, out, M, OUT_DIM, HIDDEN);
}

// round 12
// speedup vs baseline: 1.3865x; 1.0102x over previous
#include <cuda_runtime.h>
#include <cuda_bf16.h>
#include <math.h>
#include <stdint.h>

// ---------------- problem constants ----------------
#define BB      4
#define SS      2048
#define HIDDEN  1024
#define HEADS   16
#define DH      64
#define LAYERS  4
#define IN_DIM  512
#define OUT_DIM 1024
#define FF_DIM  4096
#define M_ROWS  (BB * SS)          // 8192

// ---------------- scratch (no allocation allowed) ----------------
__device__ float g_h  [(size_t)M_ROWS * HIDDEN];
__device__ float g_qkv[(size_t)M_ROWS * 3 * HIDDEN];
__device__ float g_y  [(size_t)M_ROWS * HIDDEN];

// pre-split weight arenas (hi/lo)
#define W_TOTAL 51904512
__device__ float g_wh[(size_t)W_TOTAL];
__device__ float g_wl[(size_t)W_TOTAL];
// split activation buffers
__device__ float g_ah[(size_t)M_ROWS * HIDDEN];   // h / ctx splits
__device__ float g_al[(size_t)M_ROWS * HIDDEN];
__device__ float g_fh[(size_t)M_ROWS * FF_DIM];   // x split, ff split
__device__ float g_fl[(size_t)M_ROWS * FF_DIM];

// ---------------- tf32 helpers ----------------
__device__ __forceinline__ float tf32r(float x) {
    uint32_t u;
    asm("cvt.rna.tf32.f32 %0, %1;" : "=r"(u) : "f"(x));
    return __uint_as_float(u);
}
__device__ __forceinline__ void split4(float4 v, float4& hi, float4& lo) {
    hi.x = tf32r(v.x); lo.x = tf32r(v.x - hi.x);
    hi.y = tf32r(v.y); lo.y = tf32r(v.y - hi.y);
    hi.z = tf32r(v.z); lo.z = tf32r(v.z - hi.z);
    hi.w = tf32r(v.w); lo.w = tf32r(v.w - hi.w);
}
// D = A(16x8,row) * B(8x8,col) + D, tf32 inputs, f32 accum
__device__ __forceinline__ void mma_tf32(float* c, const float* a, const float* b) {
    asm volatile(
        "mma.sync.aligned.m16n8k8.row.col.f32.tf32.tf32.f32 "
        "{%0,%1,%2,%3}, {%4,%5,%6,%7}, {%8,%9}, {%0,%1,%2,%3};\n"
        : "+f"(c[0]), "+f"(c[1]), "+f"(c[2]), "+f"(c[3])
        : "r"(__float_as_uint(a[0])), "r"(__float_as_uint(a[1])),
          "r"(__float_as_uint(a[2])), "r"(__float_as_uint(a[3])),
          "r"(__float_as_uint(b[0])), "r"(__float_as_uint(b[1])));
}
// 3xTF32: c += Ahi*Bhi + Ahi*Blo + Alo*Bhi
__device__ __forceinline__ void mma3(float* c, const float* ah, const float* al,
                                     const float* bh, const float* bl) {
    mma_tf32(c, ah, bl);
    mma_tf32(c, al, bh);
    mma_tf32(c, ah, bh);
}

__device__ __forceinline__ uint32_t smem_u32(const void* p) {
    uint32_t a;
    asm("{ .reg .u64 t; cvta.to.shared.u64 t, %1; cvt.u32.u64 %0, t; }"
        : "=r"(a) : "l"(p));
    return a;
}
#define CP16(dst_u32, src_ptr) \
    asm volatile("cp.async.cg.shared.global [%0], [%1], 16;" :: "r"(dst_u32), "l"(src_ptr))
#define CP_COMMIT()  asm volatile("cp.async.commit_group;")
#define CP_WAIT1()   asm volatile("cp.async.wait_group 1;")
#define CP_WAIT0()   asm volatile("cp.async.wait_group 0;")

// =================================================================
// One-shot weight split: all 6 weight tensors into the hi/lo arenas.
// =================================================================
#define N0_F4 (IN_DIM * HIDDEN / 4)
#define N1_F4 (N0_F4 + LAYERS * HIDDEN * 3 * HIDDEN / 4)
#define N2_F4 (N1_F4 + LAYERS * HIDDEN * HIDDEN / 4)
#define N3_F4 (N2_F4 + LAYERS * HIDDEN * FF_DIM / 4)
#define N4_F4 (N3_F4 + LAYERS * FF_DIM * HIDDEN / 4)
#define N5_F4 (N4_F4 + HIDDEN * OUT_DIM / 4)      // = W_TOTAL/4

__global__ void __launch_bounds__(256)
split_weights(const float* __restrict__ s0, const float* __restrict__ s1,
              const float* __restrict__ s2, const float* __restrict__ s3,
              const float* __restrict__ s4, const float* __restrict__ s5,
              float* __restrict__ wh, float* __restrict__ wl)
{
    size_t i = (size_t)blockIdx.x * 256 + threadIdx.x;
    if (i >= (size_t)N5_F4) return;
    const float* src; size_t base;
    if      (i < N0_F4) { src = s0; base = 0; }
    else if (i < N1_F4) { src = s1; base = N0_F4; }
    else if (i < N2_F4) { src = s2; base = N1_F4; }
    else if (i < N3_F4) { src = s3; base = N2_F4; }
    else if (i < N4_F4) { src = s4; base = N3_F4; }
    else                { src = s5; base = N4_F4; }
    float4 v = ((const float4*)src)[i - base];
    float4 h, l;
    split4(v, h, l);
    ((float4*)wh)[i] = h;
    ((float4*)wl)[i] = l;
}

// =================================================================
// Elementwise hi/lo split (used only for x)
// =================================================================
__global__ void __launch_bounds__(256)
split_kernel(const float* __restrict__ src, float* __restrict__ hi,
             float* __restrict__ lo, int n4)
{
    int i = blockIdx.x * blockDim.x + threadIdx.x;
    if (i < n4) {
        float4 v = ((const float4*)src)[i];
        float4 h, l;
        split4(v, h, l);
        ((float4*)hi)[i] = h;
        ((float4*)lo)[i] = l;
    }
}

// =================================================================
// Tensor-core GEMM (3xTF32), pre-split inputs, cp.async 3-stage.
// EPI: 0 = bias, 1 = bias+relu, 2 = bias then *32 + posenc
// SOUT: 0 = write C fp32; 1 = write Ch/Cl split; 2 = both
// =================================================================
#define AS_F  (128 * 20)
#define BS_F  (16 * 132)
#define STG_F (2 * AS_F + 2 * BS_F)                 // 9344 floats per stage
#define GEMM_SMEM (3 * STG_F * sizeof(float))       // 112128 B

template<int EPI, int SOUT>
__global__ void __launch_bounds__(256, 2)
gemm_tc(const float* __restrict__ Ah, const float* __restrict__ Al,
        const float* __restrict__ Bh, const float* __restrict__ Bl,
        const float* __restrict__ bias, float* __restrict__ C,
        float* __restrict__ Ch, float* __restrict__ Cl,
        int M, int N, int K)
{
    extern __shared__ __align__(16) float smp[];
    const uint32_t sbase = smem_u32(smp);

    const int tid = threadIdx.x;
    const int cb = blockIdx.x * 128;
    const int rb = blockIdx.y * 128;

    const int arow = tid >> 1;           // 0..127
    const int ac0  = (tid & 1) * 8;      // 0 or 8
    const int br0  = tid >> 5;           // 0..7
    const int bc   = (tid & 31) * 4;     // 0..124

    const float* gAh = Ah + (size_t)(rb + arow) * K + ac0;
    const float* gAl = Al + (size_t)(rb + arow) * K + ac0;
    const float* gBh = Bh + (size_t)br0 * N + cb + bc;
    const float* gBl = Bl + (size_t)br0 * N + cb + bc;

    const int wid = tid >> 5, lane = tid & 31;
    const int grp = lane >> 2, t4 = lane & 3;
    const int m0 = (wid >> 2) * 64;
    const int n0 = (wid & 3) * 32;

    const uint32_t oAh = (uint32_t)(arow * 20 + ac0) * 4;
    const uint32_t oAl = oAh + AS_F * 4;
    const uint32_t oBh = (uint32_t)(2 * AS_F + br0 * 132 + bc) * 4;
    const uint32_t oBl = oBh + BS_F * 4;

    auto issue_stage = [&](int s, int k0) {
        uint32_t sb = sbase + (uint32_t)(s * STG_F) * 4;
        const float* a_h = gAh + k0;
        const float* a_l = gAl + k0;
        CP16(sb + oAh,      a_h);
        CP16(sb + oAh + 16, a_h + 4);
        CP16(sb + oAl,      a_l);
        CP16(sb + oAl + 16, a_l + 4);
        const float* b_h = gBh + (size_t)k0 * N;
        const float* b_l = gBl + (size_t)k0 * N;
        CP16(sb + oBh, b_h);
        CP16(sb + oBh + 8 * 132 * 4, b_h + (size_t)8 * N);
        CP16(sb + oBl, b_l);
        CP16(sb + oBl + 8 * 132 * 4, b_l + (size_t)8 * N);
        CP_COMMIT();
    };

    float acc[4][4][4];
#pragma unroll
    for (int mt = 0; mt < 4; mt++)
#pragma unroll
        for (int nt = 0; nt < 4; nt++)
#pragma unroll
            for (int j = 0; j < 4; j++) acc[mt][nt][j] = 0.f;

    const int ntile = K / 16;
    issue_stage(0, 0);
    if (ntile > 1) issue_stage(1, 16);

    for (int i = 0; i < ntile; i++) {
        if (i + 1 < ntile) { CP_WAIT1(); } else { CP_WAIT0(); }
        __syncthreads();

        if (i + 2 < ntile) issue_stage((i + 2) % 3, (i + 2) * 16);

        const float* Ahs = smp + (i % 3) * STG_F;
        const float* Als = Ahs + AS_F;
        const float* Bhs = Als + AS_F;
        const float* Bls = Bhs + BS_F;

#pragma unroll
        for (int k8 = 0; k8 < 16; k8 += 8) {
            float ah[4][4], al[4][4], bh[4][2], bl[4][2];
#pragma unroll
            for (int mt = 0; mt < 4; mt++) {
                int mr = m0 + mt * 16 + grp;
                ah[mt][0] = Ahs[mr * 20 + k8 + t4];
                ah[mt][1] = Ahs[(mr + 8) * 20 + k8 + t4];
                ah[mt][2] = Ahs[mr * 20 + k8 + t4 + 4];
                ah[mt][3] = Ahs[(mr + 8) * 20 + k8 + t4 + 4];
                al[mt][0] = Als[mr * 20 + k8 + t4];
                al[mt][1] = Als[(mr + 8) * 20 + k8 + t4];
                al[mt][2] = Als[mr * 20 + k8 + t4 + 4];
                al[mt][3] = Als[(mr + 8) * 20 + k8 + t4 + 4];
            }
#pragma unroll
            for (int nt = 0; nt < 4; nt++) {
                int nc = n0 + nt * 8 + grp;
                bh[nt][0] = Bhs[(k8 + t4) * 132 + nc];
                bh[nt][1] = Bhs[(k8 + t4 + 4) * 132 + nc];
                bl[nt][0] = Bls[(k8 + t4) * 132 + nc];
                bl[nt][1] = Bls[(k8 + t4 + 4) * 132 + nc];
            }
#pragma unroll
            for (int mt = 0; mt < 4; mt++)
#pragma unroll
                for (int nt = 0; nt < 4; nt++)
                    mma3(acc[mt][nt], ah[mt], al[mt], bh[nt], bl[nt]);
        }
        __syncthreads();
    }

    // ---- epilogue ----
#pragma unroll
    for (int mt = 0; mt < 4; mt++) {
#pragma unroll
        for (int nt = 0; nt < 4; nt++) {
            int col = cb + n0 + nt * 8 + 2 * t4;
            float b0 = bias[col], b1 = bias[col + 1];
#pragma unroll
            for (int half = 0; half < 2; half++) {
                int row = rb + m0 + mt * 16 + grp + half * 8;
                float c0 = acc[mt][nt][half * 2 + 0] + b0;
                float c1 = acc[mt][nt][half * 2 + 1] + b1;
                if (EPI == 1) { c0 = fmaxf(c0, 0.f); c1 = fmaxf(c1, 0.f); }
                if (EPI == 2) {
                    int srow = row & (SS - 1);
                    float f0 = expf(-9.210340371976184f * (float)(col & ~1) * (1.0f / 1024.0f));
                    float f1 = expf(-9.210340371976184f * (float)((col + 1) & ~1) * (1.0f / 1024.0f));
                    float a0 = (float)srow * f0, a1 = (float)srow * f1;
                    float p0 = (col & 1) ? cosf(a0) : sinf(a0);
                    float p1 = ((col + 1) & 1) ? cosf(a1) : sinf(a1);
                    c0 = c0 * 32.0f + p0;
                    c1 = c1 * 32.0f + p1;
                }
                size_t idx = (size_t)row * N + col;
                if (SOUT != 1) {
                    float2 o = {c0, c1};
                    *(float2*)(C + idx) = o;
                }
                if (SOUT >= 1) {
                    float h0 = tf32r(c0), h1 = tf32r(c1);
                    float2 oh = {h0, h1};
                    float2 ol = {tf32r(c0 - h0), tf32r(c1 - h1)};
                    *(float2*)(Ch + idx) = oh;
                    *(float2*)(Cl + idx) = ol;
                }
            }
        }
    }
}

// =================================================================
// Flash attention, 3xTF32 tensor cores, register-prefetched K/V.
// Writes ctx pre-split (hi/lo) for the out-projection GEMM.
// =================================================================
#define ASTR 68
#define ATTN_SMEM ((2 * 128 * ASTR + 2 * 64 * ASTR + 2 * 64 * ASTR + 2 * 128 * ASTR) * sizeof(float))  // 208896

__global__ void __launch_bounds__(256)
attn_tc(const float* __restrict__ qkv, float* __restrict__ ctxh,
        float* __restrict__ ctxl)
{
    extern __shared__ float sm[];
    float* Qh = sm;                  // [128][68]
    float* Ql = Qh + 128 * ASTR;
    float* Kh = Ql + 128 * ASTR;     // [64][68]
    float* Kl = Kh + 64 * ASTR;
    float* Vh = Kl + 64 * ASTR;      // [64][68]
    float* Vl = Vh + 64 * ASTR;
    float* Ph = Vl + 64 * ASTR;      // [128][68]
    float* Pl = Ph + 128 * ASTR;

    const int tid = threadIdx.x;
    const int q0 = blockIdx.x * 128;
    const int h  = blockIdx.y;
    const int b  = blockIdx.z;

    const int wid = tid >> 5, lane = tid & 31;
    const int grp = lane >> 2, t4 = lane & 3;
    const int mw = wid * 16;

    const int kv_r = tid >> 4;
    const int kv_c = (tid & 15) * 4;

    // ---- load Q tile (128 x 64), hi/lo split ----
    {
        const float* qbase = qkv + (size_t)(b * SS + q0) * 3 * HIDDEN + h * DH;
#pragma unroll
        for (int u = 0; u < 8; u++) {
            int idx = tid + u * 256;
            int r = idx >> 4, c = (idx & 15) * 4;
            float4 v = *(const float4*)(qbase + (size_t)r * 3 * HIDDEN + c);
            float4 hi, lo;
            split4(v, hi, lo);
            *(float4*)&Qh[r * ASTR + c] = hi;
            *(float4*)&Ql[r * ASTR + c] = lo;
        }
    }

    float out[8][4];
    float mi0 = -1e30f, mi1 = -1e30f, li0 = 0.f, li1 = 0.f;
#pragma unroll
    for (int nt = 0; nt < 8; nt++)
#pragma unroll
        for (int j = 0; j < 4; j++) out[nt][j] = 0.f;

    float4 kvr[4], vvr[4];
    {
        const float* kb = qkv + ((size_t)(b * SS) * 3 + 1) * HIDDEN + h * DH;
        const float* vb = kb + HIDDEN;
#pragma unroll
        for (int u = 0; u < 4; u++) {
            int r = kv_r + u * 16;
            kvr[u] = *(const float4*)(kb + (size_t)r * 3 * HIDDEN + kv_c);
            vvr[u] = *(const float4*)(vb + (size_t)r * 3 * HIDDEN + kv_c);
        }
    }

    for (int kt = 0; kt < SS / 64; kt++) {
#pragma unroll
        for (int u = 0; u < 4; u++) {
            int r = kv_r + u * 16;
            float4 hi, lo;
            split4(kvr[u], hi, lo);
            *(float4*)&Kh[r * ASTR + kv_c] = hi;
            *(float4*)&Kl[r * ASTR + kv_c] = lo;
            split4(vvr[u], hi, lo);
            *(float4*)&Vh[r * ASTR + kv_c] = hi;
            *(float4*)&Vl[r * ASTR + kv_c] = lo;
        }
        __syncthreads();

        if (kt + 1 < SS / 64) {
            const float* kb = qkv + ((size_t)(b * SS + (kt + 1) * 64) * 3 + 1) * HIDDEN + h * DH;
            const float* vb = kb + HIDDEN;
#pragma unroll
            for (int u = 0; u < 4; u++) {
                int r = kv_r + u * 16;
                kvr[u] = *(const float4*)(kb + (size_t)r * 3 * HIDDEN + kv_c);
                vvr[u] = *(const float4*)(vb + (size_t)r * 3 * HIDDEN + kv_c);
            }
        }

        // ---- S = Q @ K^T ----
        float sc[8][4];
#pragma unroll
        for (int nt = 0; nt < 8; nt++)
#pragma unroll
            for (int j = 0; j < 4; j++) sc[nt][j] = 0.f;

#pragma unroll
        for (int k8 = 0; k8 < 64; k8 += 8) {
            float ah[4], al[4];
            int mr = mw + grp;
            ah[0] = Qh[mr * ASTR + k8 + t4];
            ah[1] = Qh[(mr + 8) * ASTR + k8 + t4];
            ah[2] = Qh[mr * ASTR + k8 + t4 + 4];
            ah[3] = Qh[(mr + 8) * ASTR + k8 + t4 + 4];
            al[0] = Ql[mr * ASTR + k8 + t4];
            al[1] = Ql[(mr + 8) * ASTR + k8 + t4];
            al[2] = Ql[mr * ASTR + k8 + t4 + 4];
            al[3] = Ql[(mr + 8) * ASTR + k8 + t4 + 4];
#pragma unroll
            for (int nt = 0; nt < 8; nt++) {
                float bh[2], bl[2];
                int kr = nt * 8 + grp;
                bh[0] = Kh[kr * ASTR + k8 + t4];
                bh[1] = Kh[kr * ASTR + k8 + t4 + 4];
                bl[0] = Kl[kr * ASTR + k8 + t4];
                bl[1] = Kl[kr * ASTR + k8 + t4 + 4];
                mma3(sc[nt], ah, al, bh, bl);
            }
        }

        // ---- online softmax ----
        float rm0 = -1e30f, rm1 = -1e30f;
#pragma unroll
        for (int nt = 0; nt < 8; nt++) {
#pragma unroll
            for (int j = 0; j < 4; j++) sc[nt][j] *= 0.125f;
            rm0 = fmaxf(rm0, fmaxf(sc[nt][0], sc[nt][1]));
            rm1 = fmaxf(rm1, fmaxf(sc[nt][2], sc[nt][3]));
        }
#pragma unroll
        for (int off = 1; off < 4; off <<= 1) {
            rm0 = fmaxf(rm0, __shfl_xor_sync(0xffffffffu, rm0, off));
            rm1 = fmaxf(rm1, __shfl_xor_sync(0xffffffffu, rm1, off));
        }
        float mn0 = fmaxf(mi0, rm0), mn1 = fmaxf(mi1, rm1);
        float rs0 = 0.f, rs1 = 0.f;
#pragma unroll
        for (int nt = 0; nt < 8; nt++) {
            sc[nt][0] = __expf(sc[nt][0] - mn0);
            sc[nt][1] = __expf(sc[nt][1] - mn0);
            sc[nt][2] = __expf(sc[nt][2] - mn1);
            sc[nt][3] = __expf(sc[nt][3] - mn1);
            rs0 += sc[nt][0] + sc[nt][1];
            rs1 += sc[nt][2] + sc[nt][3];
        }
#pragma unroll
        for (int off = 1; off < 4; off <<= 1) {
            rs0 += __shfl_xor_sync(0xffffffffu, rs0, off);
            rs1 += __shfl_xor_sync(0xffffffffu, rs1, off);
        }
        float al0 = __expf(mi0 - mn0), al1 = __expf(mi1 - mn1);
        li0 = li0 * al0 + rs0;
        li1 = li1 * al1 + rs1;
        mi0 = mn0; mi1 = mn1;

        int pr0 = (mw + grp) * ASTR, pr1 = (mw + grp + 8) * ASTR;
#pragma unroll
        for (int nt = 0; nt < 8; nt++) {
            out[nt][0] *= al0; out[nt][1] *= al0;
            out[nt][2] *= al1; out[nt][3] *= al1;
            int pc = nt * 8 + 2 * t4;
            float h0 = tf32r(sc[nt][0]), h1 = tf32r(sc[nt][1]);
            float h2 = tf32r(sc[nt][2]), h3 = tf32r(sc[nt][3]);
            float2 ph0 = {h0, h1}, ph1 = {h2, h3};
            float2 pl0 = {tf32r(sc[nt][0] - h0), tf32r(sc[nt][1] - h1)};
            float2 pl1 = {tf32r(sc[nt][2] - h2), tf32r(sc[nt][3] - h3)};
            *(float2*)&Ph[pr0 + pc] = ph0;
            *(float2*)&Ph[pr1 + pc] = ph1;
            *(float2*)&Pl[pr0 + pc] = pl0;
            *(float2*)&Pl[pr1 + pc] = pl1;
        }
        __syncwarp();

        // ---- out += P @ V ----
#pragma unroll
        for (int k8 = 0; k8 < 64; k8 += 8) {
            float ah[4], al[4];
            int mr = mw + grp;
            ah[0] = Ph[mr * ASTR + k8 + t4];
            ah[1] = Ph[(mr + 8) * ASTR + k8 + t4];
            ah[2] = Ph[mr * ASTR + k8 + t4 + 4];
            ah[3] = Ph[(mr + 8) * ASTR + k8 + t4 + 4];
            al[0] = Pl[mr * ASTR + k8 + t4];
            al[1] = Pl[(mr + 8) * ASTR + k8 + t4];
            al[2] = Pl[mr * ASTR + k8 + t4 + 4];
            al[3] = Pl[(mr + 8) * ASTR + k8 + t4 + 4];
#pragma unroll
            for (int nt = 0; nt < 8; nt++) {
                float bh[2], bl[2];
                int nc = nt * 8 + grp;
                bh[0] = Vh[(k8 + t4) * ASTR + nc];
                bh[1] = Vh[(k8 + t4 + 4) * ASTR + nc];
                bl[0] = Vl[(k8 + t4) * ASTR + nc];
                bl[1] = Vl[(k8 + t4 + 4) * ASTR + nc];
                mma3(out[nt], ah, al, bh, bl);
            }
        }
        __syncthreads();
    }

    // ---- write ctx pre-split ----
    float inv0 = 1.0f / li0, inv1 = 1.0f / li1;
    size_t row0 = (size_t)(b * SS + q0 + mw + grp) * HIDDEN + h * DH;
    size_t row1 = row0 + (size_t)8 * HIDDEN;
#pragma unroll
    for (int nt = 0; nt < 8; nt++) {
        int col = nt * 8 + 2 * t4;
        float v0 = out[nt][0] * inv0, v1 = out[nt][1] * inv0;
        float v2 = out[nt][2] * inv1, v3 = out[nt][3] * inv1;
        float h0 = tf32r(v0), h1 = tf32r(v1), h2 = tf32r(v2), h3 = tf32r(v3);
        float2 oh0 = {h0, h1}, oh1 = {h2, h3};
        float2 ol0 = {tf32r(v0 - h0), tf32r(v1 - h1)};
        float2 ol1 = {tf32r(v2 - h2), tf32r(v3 - h3)};
        *(float2*)&ctxh[row0 + col] = oh0;
        *(float2*)&ctxl[row0 + col] = ol0;
        *(float2*)&ctxh[row1 + col] = oh1;
        *(float2*)&ctxl[row1 + col] = ol1;
    }
}

// =================================================================
// LayerNorm: out = LN(x + res) * g + b; optional fp32 out and/or
// split (hi/lo) outputs.
// =================================================================
__global__ void __launch_bounds__(256)
ln_kernel(const float* __restrict__ x, const float* __restrict__ res,
          const float* __restrict__ g, const float* __restrict__ beta,
          float* __restrict__ out, float* __restrict__ oh,
          float* __restrict__ ol)
{
    const int row = blockIdx.x;
    const int t = threadIdx.x;

    float4 v = ((const float4*)(x + (size_t)row * HIDDEN))[t];
    if (res) {
        float4 r = ((const float4*)(res + (size_t)row * HIDDEN))[t];
        v.x += r.x; v.y += r.y; v.z += r.z; v.w += r.w;
    }
    float s  = v.x + v.y + v.z + v.w;
    float sq = v.x * v.x + v.y * v.y + v.z * v.z + v.w * v.w;

#pragma unroll
    for (int off = 16; off > 0; off >>= 1) {
        s  += __shfl_xor_sync(0xffffffffu, s,  off);
        sq += __shfl_xor_sync(0xffffffffu, sq, off);
    }
    __shared__ float ss[8], ssq[8];
    __shared__ float smean, srstd;
    int warp = t >> 5, lane = t & 31;
    if (lane == 0) { ss[warp] = s; ssq[warp] = sq; }
    __syncthreads();
    if (t == 0) {
        float S = 0.f, Q = 0.f;
#pragma unroll
        for (int i = 0; i < 8; i++) { S += ss[i]; Q += ssq[i]; }
        float mean = S * (1.0f / HIDDEN);
        float var  = Q * (1.0f / HIDDEN) - mean * mean;
        smean = mean;
        srstd = rsqrtf(var + 1e-5f);
    }
    __syncthreads();
    float mean = smean, rstd = srstd;

    float4 gg = ((const float4*)g)[t];
    float4 bb = ((const float4*)beta)[t];
    float4 o;
    o.x = (v.x - mean) * rstd * gg.x + bb.x;
    o.y = (v.y - mean) * rstd * gg.y + bb.y;
    o.z = (v.z - mean) * rstd * gg.z + bb.z;
    o.w = (v.w - mean) * rstd * gg.w + bb.w;
    if (out) ((float4*)(out + (size_t)row * HIDDEN))[t] = o;
    if (oh) {
        float4 hi, lo;
        split4(o, hi, lo);
        ((float4*)(oh + (size_t)row * HIDDEN))[t] = hi;
        ((float4*)(ol + (size_t)row * HIDDEN))[t] = lo;
    }
}

// =================================================================
// launch
// =================================================================
extern "C" void kernel_launch(void* const* d_in, const int* in_sizes, int n_in,
                              void* d_out, int out_size)
{
    const float* x     = (const float*)d_in[0];
    const float* in_W  = (const float*)d_in[1];
    const float* in_b  = (const float*)d_in[2];
    const float* qkv_W = (const float*)d_in[3];
    const float* qkv_b = (const float*)d_in[4];
    const float* out_W = (const float*)d_in[5];
    const float* out_b = (const float*)d_in[6];
    const float* ln1_g = (const float*)d_in[7];
    const float* ln1_b = (const float*)d_in[8];
    const float* ln2_g = (const float*)d_in[9];
    const float* ln2_b = (const float*)d_in[10];
    const float* ff1_W = (const float*)d_in[11];
    const float* ff1_b = (const float*)d_in[12];
    const float* ff2_W = (const float*)d_in[13];
    const float* ff2_b = (const float*)d_in[14];
    const float* fin_g = (const float*)d_in[15];
    const float* fin_b = (const float*)d_in[16];
    const float* op_W  = (const float*)d_in[17];
    const float* op_b  = (const float*)d_in[18];
    float* out = (float*)d_out;

    float *h, *qkv, *y, *wh, *wl, *ah, *al, *fh, *fl;
    cudaGetSymbolAddress((void**)&h,   g_h);
    cudaGetSymbolAddress((void**)&qkv, g_qkv);
    cudaGetSymbolAddress((void**)&y,   g_y);
    cudaGetSymbolAddress((void**)&wh,  g_wh);
    cudaGetSymbolAddress((void**)&wl,  g_wl);
    cudaGetSymbolAddress((void**)&ah,  g_ah);
    cudaGetSymbolAddress((void**)&al,  g_al);
    cudaGetSymbolAddress((void**)&fh,  g_fh);
    cudaGetSymbolAddress((void**)&fl,  g_fl);

    cudaFuncSetAttribute(attn_tc, cudaFuncAttributeMaxDynamicSharedMemorySize,
                         (int)ATTN_SMEM);
    cudaFuncSetAttribute((gemm_tc<0,0>), cudaFuncAttributeMaxDynamicSharedMemorySize, (int)GEMM_SMEM);
    cudaFuncSetAttribute((gemm_tc<1,1>), cudaFuncAttributeMaxDynamicSharedMemorySize, (int)GEMM_SMEM);
    cudaFuncSetAttribute((gemm_tc<2,2>), cudaFuncAttributeMaxDynamicSharedMemorySize, (int)GEMM_SMEM);

    const int M = M_ROWS;
    dim3 blk(256);

    // weight arena offsets (floats)
    const size_t ofs_in  = 0;
    const size_t ofs_qkv = ofs_in  + (size_t)IN_DIM * HIDDEN;
    const size_t ofs_out = ofs_qkv + (size_t)LAYERS * HIDDEN * 3 * HIDDEN;
    const size_t ofs_ff1 = ofs_out + (size_t)LAYERS * HIDDEN * HIDDEN;
    const size_t ofs_ff2 = ofs_ff1 + (size_t)LAYERS * HIDDEN * FF_DIM;
    const size_t ofs_op  = ofs_ff2 + (size_t)LAYERS * FF_DIM * HIDDEN;

    // L0: all weights split in one launch
    split_weights<<<(N5_F4 + 255) / 256, blk>>>(in_W, qkv_W, out_W, ff1_W,
                                                ff2_W, op_W, wh, wl);
    // L1: x split (into fh/fl so gemm<2> can write ah/al)
    {
        int n4 = M * IN_DIM / 4;
        split_kernel<<<(n4 + 255) / 256, blk>>>(x, fh, fl, n4);
    }
    // L2: input projection + posenc; writes h fp32 AND h split
    gemm_tc<2, 2><<<dim3(HIDDEN / 128, M / 128), blk, GEMM_SMEM>>>(
        fh, fl, wh + ofs_in, wl + ofs_in, in_b, h, ah, al, M, HIDDEN, IN_DIM);

    for (int l = 0; l < LAYERS; l++) {
        const float* qb  = qkv_b + (size_t)l * 3 * HIDDEN;
        const float* ob  = out_b + (size_t)l * HIDDEN;
        const float* f1b = ff1_b + (size_t)l * FF_DIM;
        const float* f2b = ff2_b + (size_t)l * HIDDEN;
        size_t wq  = ofs_qkv + (size_t)l * HIDDEN * 3 * HIDDEN;
        size_t wo  = ofs_out + (size_t)l * HIDDEN * HIDDEN;
        size_t wf1 = ofs_ff1 + (size_t)l * HIDDEN * FF_DIM;
        size_t wf2 = ofs_ff2 + (size_t)l * FF_DIM * HIDDEN;

        // qkv projection (reads h split)
        gemm_tc<0, 0><<<dim3(3 * HIDDEN / 128, M / 128), blk, GEMM_SMEM>>>(
            ah, al, wh + wq, wl + wq, qb, qkv, nullptr, nullptr, M, 3 * HIDDEN, HIDDEN);
        // attention: writes ctx split into ah/al (qkv gemm has consumed them)
        attn_tc<<<dim3(SS / 128, HEADS, BB), blk, ATTN_SMEM>>>(qkv, ah, al);
        // out projection (reads ctx split)
        gemm_tc<0, 0><<<dim3(HIDDEN / 128, M / 128), blk, GEMM_SMEM>>>(
            ah, al, wh + wo, wl + wo, ob, y, nullptr, nullptr, M, HIDDEN, HIDDEN);
        // LN1: h = LN(h + y); writes fp32 h + h split
        ln_kernel<<<M, blk>>>(h, y, ln1_g + l * HIDDEN, ln1_b + l * HIDDEN, h, ah, al);
        // FF1 (reads h split), relu, writes ff split
        gemm_tc<1, 1><<<dim3(FF_DIM / 128, M / 128), blk, GEMM_SMEM>>>(
            ah, al, wh + wf1, wl + wf1, f1b, nullptr, fh, fl, M, FF_DIM, HIDDEN);
        // FF2 (reads ff split)
        gemm_tc<0, 0><<<dim3(HIDDEN / 128, M / 128), blk, GEMM_SMEM>>>(
            fh, fl, wh + wf2, wl + wf2, f2b, y, nullptr, nullptr, M, HIDDEN, FF_DIM);
        // LN2: h = LN(h + y); writes fp32 h + h split (for next layer's qkv)
        ln_kernel<<<M, blk>>>(h, y, ln2_g + l * HIDDEN, ln2_b + l * HIDDEN, h, ah, al);
    }

    // final LN (split only) then output projection
    ln_kernel<<<M, blk>>>(h, nullptr, fin_g, fin_b, nullptr, ah, al);
    gemm_tc<0, 0><<<dim3(OUT_DIM / 128, M / 128), blk, GEMM_SMEM>>>(
        ah, al, wh + ofs_op, wl + ofs_op, op_b, out, nullptr, nullptr, M, OUT_DIM, HIDDEN);
}

// round 14
// speedup vs baseline: 1.4707x; 1.0607x over previous
#include <cuda_runtime.h>
#include <cuda_bf16.h>
#include <math.h>
#include <stdint.h>

// ---------------- problem constants ----------------
#define BB      4
#define SS      2048
#define HIDDEN  1024
#define HEADS   16
#define DH      64
#define LAYERS  4
#define IN_DIM  512
#define OUT_DIM 1024
#define FF_DIM  4096
#define M_ROWS  (BB * SS)          // 8192

// ---------------- scratch (no allocation allowed) ----------------
__device__ float g_h  [(size_t)M_ROWS * HIDDEN];
__device__ float g_qkv[(size_t)M_ROWS * 3 * HIDDEN];
__device__ float g_y  [(size_t)M_ROWS * HIDDEN];

// pre-split weight arenas (hi/lo)
#define W_TOTAL 51904512
__device__ float g_wh[(size_t)W_TOTAL];
__device__ float g_wl[(size_t)W_TOTAL];
// split activation buffers
__device__ float g_ah[(size_t)M_ROWS * HIDDEN];   // h / ctx splits
__device__ float g_al[(size_t)M_ROWS * HIDDEN];
__device__ float g_fh[(size_t)M_ROWS * FF_DIM];   // x split, ff split
__device__ float g_fl[(size_t)M_ROWS * FF_DIM];

// ---------------- tf32 helpers ----------------
__device__ __forceinline__ float tf32r(float x) {
    uint32_t u;
    asm("cvt.rna.tf32.f32 %0, %1;" : "=r"(u) : "f"(x));
    return __uint_as_float(u);
}
__device__ __forceinline__ void split4(float4 v, float4& hi, float4& lo) {
    hi.x = tf32r(v.x); lo.x = tf32r(v.x - hi.x);
    hi.y = tf32r(v.y); lo.y = tf32r(v.y - hi.y);
    hi.z = tf32r(v.z); lo.z = tf32r(v.z - hi.z);
    hi.w = tf32r(v.w); lo.w = tf32r(v.w - hi.w);
}
// D = A(16x8,row) * B(8x8,col) + D, tf32 inputs, f32 accum
__device__ __forceinline__ void mma_tf32(float* c, const float* a, const float* b) {
    asm volatile(
        "mma.sync.aligned.m16n8k8.row.col.f32.tf32.tf32.f32 "
        "{%0,%1,%2,%3}, {%4,%5,%6,%7}, {%8,%9}, {%0,%1,%2,%3};\n"
        : "+f"(c[0]), "+f"(c[1]), "+f"(c[2]), "+f"(c[3])
        : "r"(__float_as_uint(a[0])), "r"(__float_as_uint(a[1])),
          "r"(__float_as_uint(a[2])), "r"(__float_as_uint(a[3])),
          "r"(__float_as_uint(b[0])), "r"(__float_as_uint(b[1])));
}
// 3xTF32: c += Ahi*Bhi + Ahi*Blo + Alo*Bhi  (used by attention)
__device__ __forceinline__ void mma3(float* c, const float* ah, const float* al,
                                     const float* bh, const float* bl) {
    mma_tf32(c, ah, bl);
    mma_tf32(c, al, bh);
    mma_tf32(c, ah, bh);
}

__device__ __forceinline__ uint32_t smem_u32(const void* p) {
    uint32_t a;
    asm("{ .reg .u64 t; cvta.to.shared.u64 t, %1; cvt.u32.u64 %0, t; }"
        : "=r"(a) : "l"(p));
    return a;
}
#define CP16(dst_u32, src_ptr) \
    asm volatile("cp.async.cg.shared.global [%0], [%1], 16;" :: "r"(dst_u32), "l"(src_ptr))
#define CP_COMMIT()  asm volatile("cp.async.commit_group;")
#define CP_WAIT1()   asm volatile("cp.async.wait_group 1;")
#define CP_WAIT0()   asm volatile("cp.async.wait_group 0;")

// =================================================================
// One-shot weight split: all 6 weight tensors into the hi/lo arenas.
// =================================================================
#define N0_F4 (IN_DIM * HIDDEN / 4)
#define N1_F4 (N0_F4 + LAYERS * HIDDEN * 3 * HIDDEN / 4)
#define N2_F4 (N1_F4 + LAYERS * HIDDEN * HIDDEN / 4)
#define N3_F4 (N2_F4 + LAYERS * HIDDEN * FF_DIM / 4)
#define N4_F4 (N3_F4 + LAYERS * FF_DIM * HIDDEN / 4)
#define N5_F4 (N4_F4 + HIDDEN * OUT_DIM / 4)      // = W_TOTAL/4

__global__ void __launch_bounds__(256)
split_weights(const float* __restrict__ s0, const float* __restrict__ s1,
              const float* __restrict__ s2, const float* __restrict__ s3,
              const float* __restrict__ s4, const float* __restrict__ s5,
              float* __restrict__ wh, float* __restrict__ wl)
{
    size_t i = (size_t)blockIdx.x * 256 + threadIdx.x;
    if (i >= (size_t)N5_F4) return;
    const float* src; size_t base;
    if      (i < N0_F4) { src = s0; base = 0; }
    else if (i < N1_F4) { src = s1; base = N0_F4; }
    else if (i < N2_F4) { src = s2; base = N1_F4; }
    else if (i < N3_F4) { src = s3; base = N2_F4; }
    else if (i < N4_F4) { src = s4; base = N3_F4; }
    else                { src = s5; base = N4_F4; }
    float4 v = ((const float4*)src)[i - base];
    float4 h, l;
    split4(v, h, l);
    ((float4*)wh)[i] = h;
    ((float4*)wl)[i] = l;
}

// =================================================================
// Elementwise hi/lo split (used only for x)
// =================================================================
__global__ void __launch_bounds__(256)
split_kernel(const float* __restrict__ src, float* __restrict__ hi,
             float* __restrict__ lo, int n4)
{
    int i = blockIdx.x * blockDim.x + threadIdx.x;
    if (i < n4) {
        float4 v = ((const float4*)src)[i];
        float4 h, l;
        split4(v, h, l);
        ((float4*)hi)[i] = h;
        ((float4*)lo)[i] = l;
    }
}

// =================================================================
// Tensor-core GEMM (3xTF32), pre-split inputs, cp.async 3-stage.
// EPI: 0 = bias, 1 = bias+relu, 2 = bias then *32 + posenc
// SOUT: 0 = write C fp32; 1 = write Ch/Cl split; 2 = both
// ONE barrier per k-tile; mma issued as three 16-independent passes.
// =================================================================
#define AS_F  (128 * 20)
#define BS_F  (16 * 132)
#define STG_F (2 * AS_F + 2 * BS_F)                 // 9344 floats per stage
#define GEMM_SMEM (3 * STG_F * sizeof(float))       // 112128 B

template<int EPI, int SOUT>
__global__ void __launch_bounds__(256, 2)
gemm_tc(const float* __restrict__ Ah, const float* __restrict__ Al,
        const float* __restrict__ Bh, const float* __restrict__ Bl,
        const float* __restrict__ bias, float* __restrict__ C,
        float* __restrict__ Ch, float* __restrict__ Cl,
        int M, int N, int K)
{
    extern __shared__ __align__(16) float smp[];
    const uint32_t sbase = smem_u32(smp);

    const int tid = threadIdx.x;
    const int cb = blockIdx.x * 128;
    const int rb = blockIdx.y * 128;

    const int arow = tid >> 1;           // 0..127
    const int ac0  = (tid & 1) * 8;      // 0 or 8
    const int br0  = tid >> 5;           // 0..7
    const int bc   = (tid & 31) * 4;     // 0..124

    const float* gAh = Ah + (size_t)(rb + arow) * K + ac0;
    const float* gAl = Al + (size_t)(rb + arow) * K + ac0;
    const float* gBh = Bh + (size_t)br0 * N + cb + bc;
    const float* gBl = Bl + (size_t)br0 * N + cb + bc;

    const int wid = tid >> 5, lane = tid & 31;
    const int grp = lane >> 2, t4 = lane & 3;
    const int m0 = (wid >> 2) * 64;
    const int n0 = (wid & 3) * 32;

    const uint32_t oAh = (uint32_t)(arow * 20 + ac0) * 4;
    const uint32_t oAl = oAh + AS_F * 4;
    const uint32_t oBh = (uint32_t)(2 * AS_F + br0 * 132 + bc) * 4;
    const uint32_t oBl = oBh + BS_F * 4;

    auto issue_stage = [&](int s, int k0) {
        uint32_t sb = sbase + (uint32_t)(s * STG_F) * 4;
        const float* a_h = gAh + k0;
        const float* a_l = gAl + k0;
        CP16(sb + oAh,      a_h);
        CP16(sb + oAh + 16, a_h + 4);
        CP16(sb + oAl,      a_l);
        CP16(sb + oAl + 16, a_l + 4);
        const float* b_h = gBh + (size_t)k0 * N;
        const float* b_l = gBl + (size_t)k0 * N;
        CP16(sb + oBh, b_h);
        CP16(sb + oBh + 8 * 132 * 4, b_h + (size_t)8 * N);
        CP16(sb + oBl, b_l);
        CP16(sb + oBl + 8 * 132 * 4, b_l + (size_t)8 * N);
        CP_COMMIT();
    };

    float acc[4][4][4];
#pragma unroll
    for (int mt = 0; mt < 4; mt++)
#pragma unroll
        for (int nt = 0; nt < 4; nt++)
#pragma unroll
            for (int j = 0; j < 4; j++) acc[mt][nt][j] = 0.f;

    const int ntile = K / 16;
    issue_stage(0, 0);
    if (ntile > 1) issue_stage(1, 16);

    for (int i = 0; i < ntile; i++) {
        if (i + 1 < ntile) { CP_WAIT1(); } else { CP_WAIT0(); }
        // Single barrier per k-tile. This barrier also certifies every warp
        // finished computing tile i-1, so writing stage (i+2)%3 (last read at
        // i-1) below is safe without a trailing barrier.
        __syncthreads();

        if (i + 2 < ntile) issue_stage((i + 2) % 3, (i + 2) * 16);

        const float* Ahs = smp + (i % 3) * STG_F;
        const float* Als = Ahs + AS_F;
        const float* Bhs = Als + AS_F;
        const float* Bls = Bhs + BS_F;

#pragma unroll
        for (int k8i = 0; k8i < 2; k8i++) {
            const int k8 = k8i * 8;
            float ah[4][4], al[4][4], bh[4][2], bl[4][2];
#pragma unroll
            for (int mt = 0; mt < 4; mt++) {
                int mr = m0 + mt * 16 + grp;
                ah[mt][0] = Ahs[mr * 20 + k8 + t4];
                ah[mt][1] = Ahs[(mr + 8) * 20 + k8 + t4];
                ah[mt][2] = Ahs[mr * 20 + k8 + t4 + 4];
                ah[mt][3] = Ahs[(mr + 8) * 20 + k8 + t4 + 4];
                al[mt][0] = Als[mr * 20 + k8 + t4];
                al[mt][1] = Als[(mr + 8) * 20 + k8 + t4];
                al[mt][2] = Als[mr * 20 + k8 + t4 + 4];
                al[mt][3] = Als[(mr + 8) * 20 + k8 + t4 + 4];
            }
#pragma unroll
            for (int nt = 0; nt < 4; nt++) {
                int nc = n0 + nt * 8 + grp;
                bh[nt][0] = Bhs[(k8 + t4) * 132 + nc];
                bh[nt][1] = Bhs[(k8 + t4 + 4) * 132 + nc];
                bl[nt][0] = Bls[(k8 + t4) * 132 + nc];
                bl[nt][1] = Bls[(k8 + t4 + 4) * 132 + nc];
            }
            // three passes, each 16 independent mmas (no back-to-back
            // same-accumulator chains)
#pragma unroll
            for (int mt = 0; mt < 4; mt++)
#pragma unroll
                for (int nt = 0; nt < 4; nt++)
                    mma_tf32(acc[mt][nt], ah[mt], bl[nt]);
#pragma unroll
            for (int mt = 0; mt < 4; mt++)
#pragma unroll
                for (int nt = 0; nt < 4; nt++)
                    mma_tf32(acc[mt][nt], al[mt], bh[nt]);
#pragma unroll
            for (int mt = 0; mt < 4; mt++)
#pragma unroll
                for (int nt = 0; nt < 4; nt++)
                    mma_tf32(acc[mt][nt], ah[mt], bh[nt]);
        }
        // no trailing barrier (see comment above)
    }

    // ---- epilogue ----
#pragma unroll
    for (int mt = 0; mt < 4; mt++) {
#pragma unroll
        for (int nt = 0; nt < 4; nt++) {
            int col = cb + n0 + nt * 8 + 2 * t4;
            float b0 = bias[col], b1 = bias[col + 1];
#pragma unroll
            for (int half = 0; half < 2; half++) {
                int row = rb + m0 + mt * 16 + grp + half * 8;
                float c0 = acc[mt][nt][half * 2 + 0] + b0;
                float c1 = acc[mt][nt][half * 2 + 1] + b1;
                if (EPI == 1) { c0 = fmaxf(c0, 0.f); c1 = fmaxf(c1, 0.f); }
                if (EPI == 2) {
                    int srow = row & (SS - 1);
                    float f0 = expf(-9.210340371976184f * (float)(col & ~1) * (1.0f / 1024.0f));
                    float f1 = expf(-9.210340371976184f * (float)((col + 1) & ~1) * (1.0f / 1024.0f));
                    float a0 = (float)srow * f0, a1 = (float)srow * f1;
                    float p0 = (col & 1) ? cosf(a0) : sinf(a0);
                    float p1 = ((col + 1) & 1) ? cosf(a1) : sinf(a1);
                    c0 = c0 * 32.0f + p0;
                    c1 = c1 * 32.0f + p1;
                }
                size_t idx = (size_t)row * N + col;
                if (SOUT != 1) {
                    float2 o = {c0, c1};
                    *(float2*)(C + idx) = o;
                }
                if (SOUT >= 1) {
                    float h0 = tf32r(c0), h1 = tf32r(c1);
                    float2 oh = {h0, h1};
                    float2 ol = {tf32r(c0 - h0), tf32r(c1 - h1)};
                    *(float2*)(Ch + idx) = oh;
                    *(float2*)(Cl + idx) = ol;
                }
            }
        }
    }
}

// =================================================================
// Flash attention, 3xTF32 tensor cores, register-prefetched K/V.
// Writes ctx pre-split (hi/lo) for the out-projection GEMM.
// =================================================================
#define ASTR 68
#define ATTN_SMEM ((2 * 128 * ASTR + 2 * 64 * ASTR + 2 * 64 * ASTR + 2 * 128 * ASTR) * sizeof(float))  // 208896

__global__ void __launch_bounds__(256)
attn_tc(const float* __restrict__ qkv, float* __restrict__ ctxh,
        float* __restrict__ ctxl)
{
    extern __shared__ float sm[];
    float* Qh = sm;                  // [128][68]
    float* Ql = Qh + 128 * ASTR;
    float* Kh = Ql + 128 * ASTR;     // [64][68]
    float* Kl = Kh + 64 * ASTR;
    float* Vh = Kl + 64 * ASTR;      // [64][68]
    float* Vl = Vh + 64 * ASTR;
    float* Ph = Vl + 64 * ASTR;      // [128][68]
    float* Pl = Ph + 128 * ASTR;

    const int tid = threadIdx.x;
    const int q0 = blockIdx.x * 128;
    const int h  = blockIdx.y;
    const int b  = blockIdx.z;

    const int wid = tid >> 5, lane = tid & 31;
    const int grp = lane >> 2, t4 = lane & 3;
    const int mw = wid * 16;

    const int kv_r = tid >> 4;
    const int kv_c = (tid & 15) * 4;

    // ---- load Q tile (128 x 64), hi/lo split ----
    {
        const float* qbase = qkv + (size_t)(b * SS + q0) * 3 * HIDDEN + h * DH;
#pragma unroll
        for (int u = 0; u < 8; u++) {
            int idx = tid + u * 256;
            int r = idx >> 4, c = (idx & 15) * 4;
            float4 v = *(const float4*)(qbase + (size_t)r * 3 * HIDDEN + c);
            float4 hi, lo;
            split4(v, hi, lo);
            *(float4*)&Qh[r * ASTR + c] = hi;
            *(float4*)&Ql[r * ASTR + c] = lo;
        }
    }

    float out[8][4];
    float mi0 = -1e30f, mi1 = -1e30f, li0 = 0.f, li1 = 0.f;
#pragma unroll
    for (int nt = 0; nt < 8; nt++)
#pragma unroll
        for (int j = 0; j < 4; j++) out[nt][j] = 0.f;

    float4 kvr[4], vvr[4];
    {
        const float* kb = qkv + ((size_t)(b * SS) * 3 + 1) * HIDDEN + h * DH;
        const float* vb = kb + HIDDEN;
#pragma unroll
        for (int u = 0; u < 4; u++) {
            int r = kv_r + u * 16;
            kvr[u] = *(const float4*)(kb + (size_t)r * 3 * HIDDEN + kv_c);
            vvr[u] = *(const float4*)(vb + (size_t)r * 3 * HIDDEN + kv_c);
        }
    }

    for (int kt = 0; kt < SS / 64; kt++) {
#pragma unroll
        for (int u = 0; u < 4; u++) {
            int r = kv_r + u * 16;
            float4 hi, lo;
            split4(kvr[u], hi, lo);
            *(float4*)&Kh[r * ASTR + kv_c] = hi;
            *(float4*)&Kl[r * ASTR + kv_c] = lo;
            split4(vvr[u], hi, lo);
            *(float4*)&Vh[r * ASTR + kv_c] = hi;
            *(float4*)&Vl[r * ASTR + kv_c] = lo;
        }
        __syncthreads();

        if (kt + 1 < SS / 64) {
            const float* kb = qkv + ((size_t)(b * SS + (kt + 1) * 64) * 3 + 1) * HIDDEN + h * DH;
            const float* vb = kb + HIDDEN;
#pragma unroll
            for (int u = 0; u < 4; u++) {
                int r = kv_r + u * 16;
                kvr[u] = *(const float4*)(kb + (size_t)r * 3 * HIDDEN + kv_c);
                vvr[u] = *(const float4*)(vb + (size_t)r * 3 * HIDDEN + kv_c);
            }
        }

        // ---- S = Q @ K^T ----
        float sc[8][4];
#pragma unroll
        for (int nt = 0; nt < 8; nt++)
#pragma unroll
            for (int j = 0; j < 4; j++) sc[nt][j] = 0.f;

#pragma unroll
        for (int k8 = 0; k8 < 64; k8 += 8) {
            float ah[4], al[4];
            int mr = mw + grp;
            ah[0] = Qh[mr * ASTR + k8 + t4];
            ah[1] = Qh[(mr + 8) * ASTR + k8 + t4];
            ah[2] = Qh[mr * ASTR + k8 + t4 + 4];
            ah[3] = Qh[(mr + 8) * ASTR + k8 + t4 + 4];
            al[0] = Ql[mr * ASTR + k8 + t4];
            al[1] = Ql[(mr + 8) * ASTR + k8 + t4];
            al[2] = Ql[mr * ASTR + k8 + t4 + 4];
            al[3] = Ql[(mr + 8) * ASTR + k8 + t4 + 4];
#pragma unroll
            for (int nt = 0; nt < 8; nt++) {
                float bh[2], bl[2];
                int kr = nt * 8 + grp;
                bh[0] = Kh[kr * ASTR + k8 + t4];
                bh[1] = Kh[kr * ASTR + k8 + t4 + 4];
                bl[0] = Kl[kr * ASTR + k8 + t4];
                bl[1] = Kl[kr * ASTR + k8 + t4 + 4];
                mma3(sc[nt], ah, al, bh, bl);
            }
        }

        // ---- online softmax ----
        float rm0 = -1e30f, rm1 = -1e30f;
#pragma unroll
        for (int nt = 0; nt < 8; nt++) {
#pragma unroll
            for (int j = 0; j < 4; j++) sc[nt][j] *= 0.125f;
            rm0 = fmaxf(rm0, fmaxf(sc[nt][0], sc[nt][1]));
            rm1 = fmaxf(rm1, fmaxf(sc[nt][2], sc[nt][3]));
        }
#pragma unroll
        for (int off = 1; off < 4; off <<= 1) {
            rm0 = fmaxf(rm0, __shfl_xor_sync(0xffffffffu, rm0, off));
            rm1 = fmaxf(rm1, __shfl_xor_sync(0xffffffffu, rm1, off));
        }
        float mn0 = fmaxf(mi0, rm0), mn1 = fmaxf(mi1, rm1);
        float rs0 = 0.f, rs1 = 0.f;
#pragma unroll
        for (int nt = 0; nt < 8; nt++) {
            sc[nt][0] = __expf(sc[nt][0] - mn0);
            sc[nt][1] = __expf(sc[nt][1] - mn0);
            sc[nt][2] = __expf(sc[nt][2] - mn1);
            sc[nt][3] = __expf(sc[nt][3] - mn1);
            rs0 += sc[nt][0] + sc[nt][1];
            rs1 += sc[nt][2] + sc[nt][3];
        }
#pragma unroll
        for (int off = 1; off < 4; off <<= 1) {
            rs0 += __shfl_xor_sync(0xffffffffu, rs0, off);
            rs1 += __shfl_xor_sync(0xffffffffu, rs1, off);
        }
        float al0 = __expf(mi0 - mn0), al1 = __expf(mi1 - mn1);
        li0 = li0 * al0 + rs0;
        li1 = li1 * al1 + rs1;
        mi0 = mn0; mi1 = mn1;

        int pr0 = (mw + grp) * ASTR, pr1 = (mw + grp + 8) * ASTR;
#pragma unroll
        for (int nt = 0; nt < 8; nt++) {
            out[nt][0] *= al0; out[nt][1] *= al0;
            out[nt][2] *= al1; out[nt][3] *= al1;
            int pc = nt * 8 + 2 * t4;
            float h0 = tf32r(sc[nt][0]), h1 = tf32r(sc[nt][1]);
            float h2 = tf32r(sc[nt][2]), h3 = tf32r(sc[nt][3]);
            float2 ph0 = {h0, h1}, ph1 = {h2, h3};
            float2 pl0 = {tf32r(sc[nt][0] - h0), tf32r(sc[nt][1] - h1)};
            float2 pl1 = {tf32r(sc[nt][2] - h2), tf32r(sc[nt][3] - h3)};
            *(float2*)&Ph[pr0 + pc] = ph0;
            *(float2*)&Ph[pr1 + pc] = ph1;
            *(float2*)&Pl[pr0 + pc] = pl0;
            *(float2*)&Pl[pr1 + pc] = pl1;
        }
        __syncwarp();

        // ---- out += P @ V ----
#pragma unroll
        for (int k8 = 0; k8 < 64; k8 += 8) {
            float ah[4], al[4];
            int mr = mw + grp;
            ah[0] = Ph[mr * ASTR + k8 + t4];
            ah[1] = Ph[(mr + 8) * ASTR + k8 + t4];
            ah[2] = Ph[mr * ASTR + k8 + t4 + 4];
            ah[3] = Ph[(mr + 8) * ASTR + k8 + t4 + 4];
            al[0] = Pl[mr * ASTR + k8 + t4];
            al[1] = Pl[(mr + 8) * ASTR + k8 + t4];
            al[2] = Pl[mr * ASTR + k8 + t4 + 4];
            al[3] = Pl[(mr + 8) * ASTR + k8 + t4 + 4];
#pragma unroll
            for (int nt = 0; nt < 8; nt++) {
                float bh[2], bl[2];
                int nc = nt * 8 + grp;
                bh[0] = Vh[(k8 + t4) * ASTR + nc];
                bh[1] = Vh[(k8 + t4 + 4) * ASTR + nc];
                bl[0] = Vl[(k8 + t4) * ASTR + nc];
                bl[1] = Vl[(k8 + t4 + 4) * ASTR + nc];
                mma3(out[nt], ah, al, bh, bl);
            }
        }
        __syncthreads();
    }

    // ---- write ctx pre-split ----
    float inv0 = 1.0f / li0, inv1 = 1.0f / li1;
    size_t row0 = (size_t)(b * SS + q0 + mw + grp) * HIDDEN + h * DH;
    size_t row1 = row0 + (size_t)8 * HIDDEN;
#pragma unroll
    for (int nt = 0; nt < 8; nt++) {
        int col = nt * 8 + 2 * t4;
        float v0 = out[nt][0] * inv0, v1 = out[nt][1] * inv0;
        float v2 = out[nt][2] * inv1, v3 = out[nt][3] * inv1;
        float h0 = tf32r(v0), h1 = tf32r(v1), h2 = tf32r(v2), h3 = tf32r(v3);
        float2 oh0 = {h0, h1}, oh1 = {h2, h3};
        float2 ol0 = {tf32r(v0 - h0), tf32r(v1 - h1)};
        float2 ol1 = {tf32r(v2 - h2), tf32r(v3 - h3)};
        *(float2*)&ctxh[row0 + col] = oh0;
        *(float2*)&ctxl[row0 + col] = ol0;
        *(float2*)&ctxh[row1 + col] = oh1;
        *(float2*)&ctxl[row1 + col] = ol1;
    }
}

// =================================================================
// LayerNorm: out = LN(x + res) * g + b; optional fp32 out and/or
// split (hi/lo) outputs.
// =================================================================
__global__ void __launch_bounds__(256)
ln_kernel(const float* __restrict__ x, const float* __restrict__ res,
          const float* __restrict__ g, const float* __restrict__ beta,
          float* __restrict__ out, float* __restrict__ oh,
          float* __restrict__ ol)
{
    const int row = blockIdx.x;
    const int t = threadIdx.x;

    float4 v = ((const float4*)(x + (size_t)row * HIDDEN))[t];
    if (res) {
        float4 r = ((const float4*)(res + (size_t)row * HIDDEN))[t];
        v.x += r.x; v.y += r.y; v.z += r.z; v.w += r.w;
    }
    float s  = v.x + v.y + v.z + v.w;
    float sq = v.x * v.x + v.y * v.y + v.z * v.z + v.w * v.w;

#pragma unroll
    for (int off = 16; off > 0; off >>= 1) {
        s  += __shfl_xor_sync(0xffffffffu, s,  off);
        sq += __shfl_xor_sync(0xffffffffu, sq, off);
    }
    __shared__ float ss[8], ssq[8];
    __shared__ float smean, srstd;
    int warp = t >> 5, lane = t & 31;
    if (lane == 0) { ss[warp] = s; ssq[warp] = sq; }
    __syncthreads();
    if (t == 0) {
        float S = 0.f, Q = 0.f;
#pragma unroll
        for (int i = 0; i < 8; i++) { S += ss[i]; Q += ssq[i]; }
        float mean = S * (1.0f / HIDDEN);
        float var  = Q * (1.0f / HIDDEN) - mean * mean;
        smean = mean;
        srstd = rsqrtf(var + 1e-5f);
    }
    __syncthreads();
    float mean = smean, rstd = srstd;

    float4 gg = ((const float4*)g)[t];
    float4 bb = ((const float4*)beta)[t];
    float4 o;
    o.x = (v.x - mean) * rstd * gg.x + bb.x;
    o.y = (v.y - mean) * rstd * gg.y + bb.y;
    o.z = (v.z - mean) * rstd * gg.z + bb.z;
    o.w = (v.w - mean) * rstd * gg.w + bb.w;
    if (out) ((float4*)(out + (size_t)row * HIDDEN))[t] = o;
    if (oh) {
        float4 hi, lo;
        split4(o, hi, lo);
        ((float4*)(oh + (size_t)row * HIDDEN))[t] = hi;
        ((float4*)(ol + (size_t)row * HIDDEN))[t] = lo;
    }
}

// =================================================================
// launch
// =================================================================
extern "C" void kernel_launch(void* const* d_in, const int* in_sizes, int n_in,
                              void* d_out, int out_size)
{
    const float* x     = (const float*)d_in[0];
    const float* in_W  = (const float*)d_in[1];
    const float* in_b  = (const float*)d_in[2];
    const float* qkv_W = (const float*)d_in[3];
    const float* qkv_b = (const float*)d_in[4];
    const float* out_W = (const float*)d_in[5];
    const float* out_b = (const float*)d_in[6];
    const float* ln1_g = (const float*)d_in[7];
    const float* ln1_b = (const float*)d_in[8];
    const float* ln2_g = (const float*)d_in[9];
    const float* ln2_b = (const float*)d_in[10];
    const float* ff1_W = (const float*)d_in[11];
    const float* ff1_b = (const float*)d_in[12];
    const float* ff2_W = (const float*)d_in[13];
    const float* ff2_b = (const float*)d_in[14];
    const float* fin_g = (const float*)d_in[15];
    const float* fin_b = (const float*)d_in[16];
    const float* op_W  = (const float*)d_in[17];
    const float* op_b  = (const float*)d_in[18];
    float* out = (float*)d_out;

    float *h, *qkv, *y, *wh, *wl, *ah, *al, *fh, *fl;
    cudaGetSymbolAddress((void**)&h,   g_h);
    cudaGetSymbolAddress((void**)&qkv, g_qkv);
    cudaGetSymbolAddress((void**)&y,   g_y);
    cudaGetSymbolAddress((void**)&wh,  g_wh);
    cudaGetSymbolAddress((void**)&wl,  g_wl);
    cudaGetSymbolAddress((void**)&ah,  g_ah);
    cudaGetSymbolAddress((void**)&al,  g_al);
    cudaGetSymbolAddress((void**)&fh,  g_fh);
    cudaGetSymbolAddress((void**)&fl,  g_fl);

    cudaFuncSetAttribute(attn_tc, cudaFuncAttributeMaxDynamicSharedMemorySize,
                         (int)ATTN_SMEM);
    cudaFuncSetAttribute((gemm_tc<0,0>), cudaFuncAttributeMaxDynamicSharedMemorySize, (int)GEMM_SMEM);
    cudaFuncSetAttribute((gemm_tc<1,1>), cudaFuncAttributeMaxDynamicSharedMemorySize, (int)GEMM_SMEM);
    cudaFuncSetAttribute((gemm_tc<2,2>), cudaFuncAttributeMaxDynamicSharedMemorySize, (int)GEMM_SMEM);

    const int M = M_ROWS;
    dim3 blk(256);

    // weight arena offsets (floats)
    const size_t ofs_in  = 0;
    const size_t ofs_qkv = ofs_in  + (size_t)IN_DIM * HIDDEN;
    const size_t ofs_out = ofs_qkv + (size_t)LAYERS * HIDDEN * 3 * HIDDEN;
    const size_t ofs_ff1 = ofs_out + (size_t)LAYERS * HIDDEN * HIDDEN;
    const size_t ofs_ff2 = ofs_ff1 + (size_t)LAYERS * HIDDEN * FF_DIM;
    const size_t ofs_op  = ofs_ff2 + (size_t)LAYERS * FF_DIM * HIDDEN;

    // L0: all weights split in one launch
    split_weights<<<(N5_F4 + 255) / 256, blk>>>(in_W, qkv_W, out_W, ff1_W,
                                                ff2_W, op_W, wh, wl);
    // L1: x split (into fh/fl so gemm<2> can write ah/al)
    {
        int n4 = M * IN_DIM / 4;
        split_kernel<<<(n4 + 255) / 256, blk>>>(x, fh, fl, n4);
    }
    // L2: input projection + posenc; writes h fp32 AND h split
    gemm_tc<2, 2><<<dim3(HIDDEN / 128, M / 128), blk, GEMM_SMEM>>>(
        fh, fl, wh + ofs_in, wl + ofs_in, in_b, h, ah, al, M, HIDDEN, IN_DIM);

    for (int l = 0; l < LAYERS; l++) {
        const float* qb  = qkv_b + (size_t)l * 3 * HIDDEN;
        const float* ob  = out_b + (size_t)l * HIDDEN;
        const float* f1b = ff1_b + (size_t)l * FF_DIM;
        const float* f2b = ff2_b + (size_t)l * HIDDEN;
        size_t wq  = ofs_qkv + (size_t)l * HIDDEN * 3 * HIDDEN;
        size_t wo  = ofs_out + (size_t)l * HIDDEN * HIDDEN;
        size_t wf1 = ofs_ff1 + (size_t)l * HIDDEN * FF_DIM;
        size_t wf2 = ofs_ff2 + (size_t)l * FF_DIM * HIDDEN;

        // qkv projection (reads h split)
        gemm_tc<0, 0><<<dim3(3 * HIDDEN / 128, M / 128), blk, GEMM_SMEM>>>(
            ah, al, wh + wq, wl + wq, qb, qkv, nullptr, nullptr, M, 3 * HIDDEN, HIDDEN);
        // attention: writes ctx split into ah/al (qkv gemm has consumed them)
        attn_tc<<<dim3(SS / 128, HEADS, BB), blk, ATTN_SMEM>>>(qkv, ah, al);
        // out projection (reads ctx split)
        gemm_tc<0, 0><<<dim3(HIDDEN / 128, M / 128), blk, GEMM_SMEM>>>(
            ah, al, wh + wo, wl + wo, ob, y, nullptr, nullptr, M, HIDDEN, HIDDEN);
        // LN1: h = LN(h + y); writes fp32 h + h split
        ln_kernel<<<M, blk>>>(h, y, ln1_g + l * HIDDEN, ln1_b + l * HIDDEN, h, ah, al);
        // FF1 (reads h split), relu, writes ff split
        gemm_tc<1, 1><<<dim3(FF_DIM / 128, M / 128), blk, GEMM_SMEM>>>(
            ah, al, wh + wf1, wl + wf1, f1b, nullptr, fh, fl, M, FF_DIM, HIDDEN);
        // FF2 (reads ff split)
        gemm_tc<0, 0><<<dim3(HIDDEN / 128, M / 128), blk, GEMM_SMEM>>>(
            fh, fl, wh + wf2, wl + wf2, f2b, y, nullptr, nullptr, M, HIDDEN, FF_DIM);
        // LN2: h = LN(h + y); writes fp32 h + h split (for next layer's qkv)
        ln_kernel<<<M, blk>>>(h, y, ln2_g + l * HIDDEN, ln2_b + l * HIDDEN, h, ah, al);
    }

    // final LN (split only) then output projection
    ln_kernel<<<M, blk>>>(h, nullptr, fin_g, fin_b, nullptr, ah, al);
    gemm_tc<0, 0><<<dim3(OUT_DIM / 128, M / 128), blk, GEMM_SMEM>>>(
        ah, al, wh + ofs_op, wl + ofs_op, op_b, out, nullptr, nullptr, M, OUT_DIM, HIDDEN);
}